// round 1
// baseline (speedup 1.0000x reference)
#include <cuda_runtime.h>
#include <cuda_bf16.h>
#include <math.h>

// ---------------- problem constants ----------------
#define D_MODEL 1024
#define D_STATE 16
#define D_CONV 4
#define D_INNER 2048
#define DT_RANK 64
#define B_SZ 2
#define SEQ 1024
#define NROWS (B_SZ * SEQ)          // 2048
#define XDBL_N (DT_RANK + 2 * D_STATE)  // 96

// ---------------- scratch (device globals; no allocation allowed) ----------
__device__ float g_xz[NROWS * 2 * D_INNER];     // 32 MB : [row, 4096] (x_e | z)
__device__ float g_xc[NROWS * D_INNER];         // 16 MB : silu(conv(x_e))
__device__ float g_zs[NROWS * D_INNER];         // 16 MB : silu(z)
__device__ float g_xdbl[NROWS * XDBL_N];        // 768 KB: [row, 96] = dt_r|B|C
__device__ float g_delta[NROWS * D_INNER];      // 16 MB : softplus(...)
__device__ float g_y[NROWS * D_INNER];          // 16 MB : scan output

// ---------------- tiled fp32 GEMM: C[M,N] = A[M,K] @ B[K,N] ----------------
// EPI==0: plain store. EPI==1: v += bias[col]; v = softplus(v).
#define BM 128
#define BN 128
#define BK 8

template <int EPI>
__global__ __launch_bounds__(256)
void sgemm128(const float* __restrict__ A, const float* __restrict__ B,
              const float* __restrict__ bias, float* __restrict__ C,
              int M, int N, int K, int lda, int ldb, int ldc)
{
    __shared__ float As[BK][BM];
    __shared__ float Bs[BK][BN];

    const int tid  = threadIdx.x;
    const int brow = blockIdx.y * BM;
    const int bcol = blockIdx.x * BN;

    // A tile loader: 128 rows x 8 k, one float4 per thread
    const int arow = tid >> 1;
    const int acol = (tid & 1) << 2;
    // B tile loader: 8 k x 128 cols, one float4 per thread
    const int bkr  = tid >> 5;
    const int bcl  = (tid & 31) << 2;
    // compute mapping: 16x16 thread grid, 8x8 micro-tile
    const int tx = (tid & 15) << 3;
    const int ty = (tid >> 4) << 3;

    float acc[8][8];
#pragma unroll
    for (int i = 0; i < 8; i++)
#pragma unroll
        for (int j = 0; j < 8; j++) acc[i][j] = 0.f;

    const float* Aptr = A + (size_t)(brow + arow) * lda + acol;
    const float* Bptr = B + (size_t)bkr * ldb + bcol + bcl;

    for (int k0 = 0; k0 < K; k0 += BK) {
        float4 av = *(const float4*)(Aptr + k0);
        float4 bv = *(const float4*)(Bptr + (size_t)k0 * ldb);
        As[acol + 0][arow] = av.x;
        As[acol + 1][arow] = av.y;
        As[acol + 2][arow] = av.z;
        As[acol + 3][arow] = av.w;
        *(float4*)&Bs[bkr][bcl] = bv;
        __syncthreads();

#pragma unroll
        for (int kk = 0; kk < BK; kk++) {
            float ar[8], br[8];
#pragma unroll
            for (int i = 0; i < 8; i++) ar[i] = As[kk][ty + i];
#pragma unroll
            for (int j = 0; j < 8; j++) br[j] = Bs[kk][tx + j];
#pragma unroll
            for (int i = 0; i < 8; i++)
#pragma unroll
                for (int j = 0; j < 8; j++)
                    acc[i][j] = fmaf(ar[i], br[j], acc[i][j]);
        }
        __syncthreads();
    }

#pragma unroll
    for (int i = 0; i < 8; i++) {
        const int row = brow + ty + i;
#pragma unroll
        for (int j = 0; j < 8; j++) {
            const int col = bcol + tx + j;
            float v = acc[i][j];
            if (EPI == 1) {
                v += bias[col];
                v = (v > 20.f) ? v : log1pf(__expf(v));  // softplus
            }
            C[(size_t)row * ldc + col] = v;
        }
    }
}

// ---------- depthwise causal conv (k=4) + SiLU, plus silu(z) precompute ----
__global__ __launch_bounds__(256)
void conv_silu_kernel(const float* __restrict__ conv_w, const float* __restrict__ conv_b)
{
    int idx = blockIdx.x * blockDim.x + threadIdx.x;
    if (idx >= NROWS * D_INNER) return;
    const int d   = idx & (D_INNER - 1);
    const int row = idx >> 11;            // b*SEQ + l
    const int l   = row & (SEQ - 1);

    const float w0 = conv_w[d * 4 + 0];
    const float w1 = conv_w[d * 4 + 1];
    const float w2 = conv_w[d * 4 + 2];
    const float w3 = conv_w[d * 4 + 3];

    const float* xe = g_xz + (size_t)row * (2 * D_INNER) + d;
    float acc = conv_b[d];
    acc = fmaf(w3, xe[0], acc);
    if (l >= 1) acc = fmaf(w2, xe[-(2 * D_INNER)], acc);
    if (l >= 2) acc = fmaf(w1, xe[-2 * (2 * D_INNER)], acc);
    if (l >= 3) acc = fmaf(w0, xe[-3 * (2 * D_INNER)], acc);

    g_xc[idx] = acc / (1.f + __expf(-acc));          // silu

    const float zv = g_xz[(size_t)row * (2 * D_INNER) + D_INNER + d];
    g_zs[idx] = zv / (1.f + __expf(-zv));            // silu(z)
}

// ---------- small-N GEMM: g_xdbl[2048,96] = g_xc[2048,2048] @ W_x[2048,96] --
__global__ __launch_bounds__(256)
void gemm_n96(const float* __restrict__ Wx)
{
    __shared__ float Bs[64][32];
    const int tx  = threadIdx.x;           // 0..31 -> col within 32-block
    const int ty  = threadIdx.y;           // 0..7  -> row within 8-block
    const int tid = ty * 32 + tx;
    const int col = blockIdx.x * 32 + tx;  // 0..95
    const int row = blockIdx.y * 8 + ty;   // 0..2047

    float acc = 0.f;
    const float* arow = g_xc + (size_t)row * D_INNER;

    for (int k0 = 0; k0 < D_INNER; k0 += 64) {
        for (int i = tid; i < 64 * 32; i += 256)
            Bs[i >> 5][i & 31] = Wx[(size_t)(k0 + (i >> 5)) * XDBL_N + blockIdx.x * 32 + (i & 31)];
        __syncthreads();
#pragma unroll
        for (int kk = 0; kk < 64; kk += 4) {
            float4 a4 = *(const float4*)(arow + k0 + kk);
            acc = fmaf(a4.x, Bs[kk + 0][tx], acc);
            acc = fmaf(a4.y, Bs[kk + 1][tx], acc);
            acc = fmaf(a4.z, Bs[kk + 2][tx], acc);
            acc = fmaf(a4.w, Bs[kk + 3][tx], acc);
        }
        __syncthreads();
    }
    if (col < XDBL_N) g_xdbl[(size_t)row * XDBL_N + col] = acc;
}

// ---------- selective scan -------------------------------------------------
// Lane layout: warp = 2 channels; lanes 0-15 -> (d0, n=lane), lanes 16-31 ->
// (d0+1, n=lane-16). h update is 1 FMA per step; exp off critical path.
// y[row,d] = (sum_n h_n * C_n + xc * D[d]) * silu(z)
__global__ __launch_bounds__(256)
void scan_kernel(const float* __restrict__ A_log, const float* __restrict__ Dp)
{
    const int lane16 = threadIdx.x & 15;
    const int chan   = (blockIdx.x << 4) | (threadIdx.x >> 4);  // d: 16 chans/block
    const int b      = blockIdx.y;

    const float Aval = -__expf(A_log[chan * D_STATE + lane16]);
    const float Dd   = Dp[chan];

    const float* dl = g_delta + (size_t)b * SEQ * D_INNER + chan;
    const float* xp = g_xc    + (size_t)b * SEQ * D_INNER + chan;
    const float* zp = g_zs    + (size_t)b * SEQ * D_INNER + chan;
    float*       yp = g_y     + (size_t)b * SEQ * D_INNER + chan;
    const float* bp = g_xdbl  + (size_t)b * SEQ * XDBL_N + DT_RANK + lane16;
    const float* cp = bp + D_STATE;

    float h = 0.f;
    for (int l = 0; l < SEQ; l++) {
        const float dv = *dl;
        const float xv = *xp;
        const float Bn = *bp;
        const float Cn = *cp;
        const float dA = __expf(dv * Aval);
        h = fmaf(dA, h, dv * xv * Bn);
        float contrib = h * Cn;
        contrib += __shfl_down_sync(0xffffffffu, contrib, 8, 16);
        contrib += __shfl_down_sync(0xffffffffu, contrib, 4, 16);
        contrib += __shfl_down_sync(0xffffffffu, contrib, 2, 16);
        contrib += __shfl_down_sync(0xffffffffu, contrib, 1, 16);
        if (lane16 == 0)
            *yp = fmaf(xv, Dd, contrib) * (*zp);
        dl += D_INNER; xp += D_INNER; zp += D_INNER; yp += D_INNER;
        bp += XDBL_N;  cp += XDBL_N;
    }
}

// ---------------- launch ----------------------------------------------------
extern "C" void kernel_launch(void* const* d_in, const int* in_sizes, int n_in,
                              void* d_out, int out_size)
{
    const float* x      = (const float*)d_in[0];
    const float* W_in   = (const float*)d_in[1];
    const float* conv_w = (const float*)d_in[2];
    const float* conv_b = (const float*)d_in[3];
    const float* W_x    = (const float*)d_in[4];
    const float* W_dt   = (const float*)d_in[5];
    const float* b_dt   = (const float*)d_in[6];
    const float* A_log  = (const float*)d_in[7];
    const float* Dp     = (const float*)d_in[8];
    const float* W_out  = (const float*)d_in[9];
    float* out = (float*)d_out;

    float *xz, *xdbl, *delta, *ybuf;
    cudaGetSymbolAddress((void**)&xz,    g_xz);
    cudaGetSymbolAddress((void**)&xdbl,  g_xdbl);
    cudaGetSymbolAddress((void**)&delta, g_delta);
    cudaGetSymbolAddress((void**)&ybuf,  g_y);

    // 1) xz = x @ W_in                 [2048,1024]@[1024,4096]
    sgemm128<0><<<dim3(2 * D_INNER / BN, NROWS / BM), 256>>>(
        x, W_in, nullptr, xz, NROWS, 2 * D_INNER, D_MODEL,
        D_MODEL, 2 * D_INNER, 2 * D_INNER);

    // 2) xc = silu(conv(x_e)+b), zs = silu(z)
    conv_silu_kernel<<<(NROWS * D_INNER + 255) / 256, 256>>>(conv_w, conv_b);

    // 3) xdbl = xc @ W_x               [2048,2048]@[2048,96]
    gemm_n96<<<dim3(3, NROWS / 8), dim3(32, 8)>>>(W_x);

    // 4) delta = softplus(xdbl[:, :64] @ W_dt + b_dt)   K=64, lda=96
    sgemm128<1><<<dim3(D_INNER / BN, NROWS / BM), 256>>>(
        xdbl, W_dt, b_dt, delta, NROWS, D_INNER, DT_RANK,
        XDBL_N, D_INNER, D_INNER);

    // 5) selective scan -> g_y (includes *silu(z) and +xc*D)
    scan_kernel<<<dim3(D_INNER / 16, B_SZ), 256>>>(A_log, Dp);

    // 6) out = y @ W_out               [2048,2048]@[2048,1024]
    sgemm128<0><<<dim3(D_MODEL / BN, NROWS / BM), 256>>>(
        ybuf, W_out, nullptr, out, NROWS, D_MODEL, D_INNER,
        D_INNER, D_MODEL, D_MODEL);
}

// round 2
// speedup vs baseline: 1.3033x; 1.3033x over previous
#include <cuda_runtime.h>
#include <cuda_bf16.h>
#include <math.h>

// ---------------- problem constants ----------------
#define D_MODEL 1024
#define D_STATE 16
#define D_CONV 4
#define D_INNER 2048
#define DT_RANK 64
#define B_SZ 2
#define SEQ 1024
#define NROWS (B_SZ * SEQ)              // 2048
#define XDBL_N (DT_RANK + 2 * D_STATE)  // 96

// ---------------- scratch (device globals; no allocation allowed) ----------
__device__ float g_xz[NROWS * 2 * D_INNER];     // 32 MB : [row, 4096] (x_e | z)
__device__ float g_xc[NROWS * D_INNER];         // 16 MB : silu(conv(x_e))
__device__ float g_zs[NROWS * D_INNER];         // 16 MB : silu(z)
__device__ float g_xdbl[NROWS * XDBL_N];        // 768 KB: [row, 96] = dt_r|B|C
__device__ float g_delta[NROWS * D_INNER];      // 16 MB : softplus(...)
__device__ float g_y[NROWS * D_INNER];          // 16 MB : scan output

// ---------------- packed f32x2 helpers (sm_103a FFMA2 path) ----------------
__device__ __forceinline__ unsigned long long pack_dup_f32(float x) {
    unsigned long long r;
    unsigned int u = __float_as_uint(x);
    asm("mov.b64 %0, {%1, %1};" : "=l"(r) : "r"(u));
    return r;
}
__device__ __forceinline__ unsigned long long fma_f32x2(
    unsigned long long a, unsigned long long b, unsigned long long c) {
    unsigned long long d;
    asm("fma.rn.f32x2 %0, %1, %2, %3;" : "=l"(d) : "l"(a), "l"(b), "l"(c));
    return d;
}
__device__ __forceinline__ float2 unpack_f32x2(unsigned long long v) {
    unsigned int lo, hi;
    asm("mov.b64 {%0, %1}, %2;" : "=r"(lo), "=r"(hi) : "l"(v));
    return make_float2(__uint_as_float(lo), __uint_as_float(hi));
}

// ---------------- tiled fp32 GEMM: C[M,N] = A[M,K] @ B[K,N] ----------------
// 128x128 tile, BK=16, double-buffered smem, packed f32x2 FMAs.
// EPI==0: plain store. EPI==1: v += bias[col]; v = softplus(v).
#define BK 16

template <int EPI>
__global__ __launch_bounds__(256, 2)
void sgemm128(const float* __restrict__ A, const float* __restrict__ B,
              const float* __restrict__ bias, float* __restrict__ C,
              int M, int N, int K, int lda, int ldb, int ldc)
{
    __shared__ __align__(16) float As[2][BK][128];
    __shared__ __align__(16) float Bs[2][BK][128];

    const int tid  = threadIdx.x;
    const int brow = blockIdx.y * 128;
    const int bcol = blockIdx.x * 128;

    // A loader: 128 rows x 16 k; thread -> (row = tid>>1, 8 k's)
    const int arow = tid >> 1;
    const int acol = (tid & 1) << 3;
    // B loader: 16 k x 128 cols; thread -> (k = tid>>4, 8 cols)
    const int bk = tid >> 4;
    const int bc = (tid & 15) << 3;
    // compute mapping: 16x16 thread grid, 8x8 micro-tile
    const int tx = (tid & 15) << 3;
    const int ty = (tid >> 4) << 3;

    const float* Ap = A + (size_t)(brow + arow) * lda + acol;
    const float* Bp = B + (size_t)bk * ldb + bcol + bc;

    unsigned long long acc[8][4];
#pragma unroll
    for (int i = 0; i < 8; i++)
#pragma unroll
        for (int j = 0; j < 4; j++) acc[i][j] = 0ull;

    float4 a0 = *(const float4*)(Ap);
    float4 a1 = *(const float4*)(Ap + 4);
    float4 b0 = *(const float4*)(Bp);
    float4 b1 = *(const float4*)(Bp + 4);

#define STORE_TILE(bufi)                                            \
    {                                                               \
        As[bufi][acol + 0][arow] = a0.x;                            \
        As[bufi][acol + 1][arow] = a0.y;                            \
        As[bufi][acol + 2][arow] = a0.z;                            \
        As[bufi][acol + 3][arow] = a0.w;                            \
        As[bufi][acol + 4][arow] = a1.x;                            \
        As[bufi][acol + 5][arow] = a1.y;                            \
        As[bufi][acol + 6][arow] = a1.z;                            \
        As[bufi][acol + 7][arow] = a1.w;                            \
        *(float4*)&Bs[bufi][bk][bc]     = b0;                       \
        *(float4*)&Bs[bufi][bk][bc + 4] = b1;                       \
    }

#define COMPUTE_TILE(bufi)                                          \
    {                                                               \
        _Pragma("unroll")                                           \
        for (int kk = 0; kk < BK; kk++) {                           \
            float4 av0 = *(const float4*)&As[bufi][kk][ty];         \
            float4 av1 = *(const float4*)&As[bufi][kk][ty + 4];     \
            ulonglong2 bq01 = *(const ulonglong2*)&Bs[bufi][kk][tx];\
            ulonglong2 bq23 = *(const ulonglong2*)&Bs[bufi][kk][tx + 4];\
            unsigned long long bq[4] = {bq01.x, bq01.y, bq23.x, bq23.y};\
            float ar[8] = {av0.x, av0.y, av0.z, av0.w,              \
                           av1.x, av1.y, av1.z, av1.w};             \
            _Pragma("unroll")                                       \
            for (int i = 0; i < 8; i++) {                           \
                unsigned long long a2 = pack_dup_f32(ar[i]);        \
                _Pragma("unroll")                                   \
                for (int j = 0; j < 4; j++)                         \
                    acc[i][j] = fma_f32x2(a2, bq[j], acc[i][j]);    \
            }                                                       \
        }                                                           \
    }

    STORE_TILE(0);
    __syncthreads();

    int buf = 0;
    for (int k0 = BK; k0 < K; k0 += BK) {
        a0 = *(const float4*)(Ap + k0);
        a1 = *(const float4*)(Ap + k0 + 4);
        b0 = *(const float4*)(Bp + (size_t)k0 * ldb);
        b1 = *(const float4*)(Bp + (size_t)k0 * ldb + 4);
        COMPUTE_TILE(buf);
        STORE_TILE(buf ^ 1);
        __syncthreads();
        buf ^= 1;
    }
    COMPUTE_TILE(buf);

#pragma unroll
    for (int i = 0; i < 8; i++) {
        const int row = brow + ty + i;
#pragma unroll
        for (int j = 0; j < 4; j++) {
            float2 v = unpack_f32x2(acc[i][j]);
            const int col = bcol + tx + 2 * j;
            if (EPI == 1) {
                v.x += bias[col];
                v.y += bias[col + 1];
                v.x = (v.x > 20.f) ? v.x : log1pf(__expf(v.x));
                v.y = (v.y > 20.f) ? v.y : log1pf(__expf(v.y));
            }
            *(float2*)&C[(size_t)row * ldc + col] = v;
        }
    }
#undef STORE_TILE
#undef COMPUTE_TILE
}

// ---------- depthwise causal conv (k=4) + SiLU, plus silu(z) precompute ----
__global__ __launch_bounds__(256)
void conv_silu_kernel(const float* __restrict__ conv_w, const float* __restrict__ conv_b)
{
    int idx = blockIdx.x * blockDim.x + threadIdx.x;
    if (idx >= NROWS * D_INNER) return;
    const int d   = idx & (D_INNER - 1);
    const int row = idx >> 11;            // b*SEQ + l
    const int l   = row & (SEQ - 1);

    const float w0 = conv_w[d * 4 + 0];
    const float w1 = conv_w[d * 4 + 1];
    const float w2 = conv_w[d * 4 + 2];
    const float w3 = conv_w[d * 4 + 3];

    const float* xe = g_xz + (size_t)row * (2 * D_INNER) + d;
    float acc = conv_b[d];
    acc = fmaf(w3, xe[0], acc);
    if (l >= 1) acc = fmaf(w2, xe[-(2 * D_INNER)], acc);
    if (l >= 2) acc = fmaf(w1, xe[-2 * (2 * D_INNER)], acc);
    if (l >= 3) acc = fmaf(w0, xe[-3 * (2 * D_INNER)], acc);

    g_xc[idx] = acc / (1.f + __expf(-acc));          // silu

    const float zv = g_xz[(size_t)row * (2 * D_INNER) + D_INNER + d];
    g_zs[idx] = zv / (1.f + __expf(-zv));            // silu(z)
}

// ---------- small-N GEMM: g_xdbl[2048,96] = g_xc[2048,2048] @ W_x[2048,96] --
__global__ __launch_bounds__(256)
void gemm_n96(const float* __restrict__ Wx)
{
    __shared__ float Bs[64][32];
    const int tx  = threadIdx.x;           // 0..31 -> col within 32-block
    const int ty  = threadIdx.y;           // 0..7  -> row within 8-block
    const int tid = ty * 32 + tx;
    const int col = blockIdx.x * 32 + tx;  // 0..95
    const int row = blockIdx.y * 8 + ty;   // 0..2047

    float acc = 0.f;
    const float* arow = g_xc + (size_t)row * D_INNER;

    for (int k0 = 0; k0 < D_INNER; k0 += 64) {
        for (int i = tid; i < 64 * 32; i += 256)
            Bs[i >> 5][i & 31] = Wx[(size_t)(k0 + (i >> 5)) * XDBL_N + blockIdx.x * 32 + (i & 31)];
        __syncthreads();
#pragma unroll
        for (int kk = 0; kk < 64; kk += 4) {
            float4 a4 = *(const float4*)(arow + k0 + kk);
            acc = fmaf(a4.x, Bs[kk + 0][tx], acc);
            acc = fmaf(a4.y, Bs[kk + 1][tx], acc);
            acc = fmaf(a4.z, Bs[kk + 2][tx], acc);
            acc = fmaf(a4.w, Bs[kk + 3][tx], acc);
        }
        __syncthreads();
    }
    if (col < XDBL_N) g_xdbl[(size_t)row * XDBL_N + col] = acc;
}

// ---------- selective scan -------------------------------------------------
// Lane layout: warp = 2 channels; lanes 0-15 -> (d0, n=lane), lanes 16-31 ->
// (d0+1, n=lane-16). h update is 1 FMA per step; exp off critical path.
// Unrolled x4: loads for 4 timesteps batched up-front (MLP), shfl trees overlap.
__global__ __launch_bounds__(256)
void scan_kernel(const float* __restrict__ A_log, const float* __restrict__ Dp)
{
    const int lane16 = threadIdx.x & 15;
    const int chan   = (blockIdx.x << 4) | (threadIdx.x >> 4);  // d: 16 chans/block
    const int b      = blockIdx.y;

    const float Aval = -__expf(A_log[chan * D_STATE + lane16]);
    const float Dd   = Dp[chan];

    const float* dl = g_delta + (size_t)b * SEQ * D_INNER + chan;
    const float* xp = g_xc    + (size_t)b * SEQ * D_INNER + chan;
    const float* zp = g_zs    + (size_t)b * SEQ * D_INNER + chan;
    float*       yp = g_y     + (size_t)b * SEQ * D_INNER + chan;
    const float* bp = g_xdbl  + (size_t)b * SEQ * XDBL_N + DT_RANK + lane16;
    const float* cp = bp + D_STATE;

    float h = 0.f;
    for (int l = 0; l < SEQ; l += 4) {
        float dv[4], xv[4], Bn[4], Cn[4], zv[4], dA[4];
#pragma unroll
        for (int u = 0; u < 4; u++) {
            dv[u] = dl[u * D_INNER];
            xv[u] = xp[u * D_INNER];
            zv[u] = zp[u * D_INNER];
            Bn[u] = bp[u * XDBL_N];
            Cn[u] = cp[u * XDBL_N];
        }
#pragma unroll
        for (int u = 0; u < 4; u++)
            dA[u] = __expf(dv[u] * Aval);

        float contrib[4];
#pragma unroll
        for (int u = 0; u < 4; u++) {
            h = fmaf(dA[u], h, dv[u] * xv[u] * Bn[u]);
            contrib[u] = h * Cn[u];
        }
#pragma unroll
        for (int u = 0; u < 4; u++) {
            contrib[u] += __shfl_down_sync(0xffffffffu, contrib[u], 8, 16);
            contrib[u] += __shfl_down_sync(0xffffffffu, contrib[u], 4, 16);
            contrib[u] += __shfl_down_sync(0xffffffffu, contrib[u], 2, 16);
            contrib[u] += __shfl_down_sync(0xffffffffu, contrib[u], 1, 16);
        }
        if (lane16 == 0) {
#pragma unroll
            for (int u = 0; u < 4; u++)
                yp[u * D_INNER] = fmaf(xv[u], Dd, contrib[u]) * zv[u];
        }
        dl += 4 * D_INNER; xp += 4 * D_INNER; zp += 4 * D_INNER; yp += 4 * D_INNER;
        bp += 4 * XDBL_N;  cp += 4 * XDBL_N;
    }
}

// ---------------- launch ----------------------------------------------------
extern "C" void kernel_launch(void* const* d_in, const int* in_sizes, int n_in,
                              void* d_out, int out_size)
{
    const float* x      = (const float*)d_in[0];
    const float* W_in   = (const float*)d_in[1];
    const float* conv_w = (const float*)d_in[2];
    const float* conv_b = (const float*)d_in[3];
    const float* W_x    = (const float*)d_in[4];
    const float* W_dt   = (const float*)d_in[5];
    const float* b_dt   = (const float*)d_in[6];
    const float* A_log  = (const float*)d_in[7];
    const float* Dp     = (const float*)d_in[8];
    const float* W_out  = (const float*)d_in[9];
    float* out = (float*)d_out;

    float *xz, *xdbl, *delta, *ybuf;
    cudaGetSymbolAddress((void**)&xz,    g_xz);
    cudaGetSymbolAddress((void**)&xdbl,  g_xdbl);
    cudaGetSymbolAddress((void**)&delta, g_delta);
    cudaGetSymbolAddress((void**)&ybuf,  g_y);

    // 1) xz = x @ W_in                 [2048,1024]@[1024,4096]
    sgemm128<0><<<dim3(2 * D_INNER / 128, NROWS / 128), 256>>>(
        x, W_in, nullptr, xz, NROWS, 2 * D_INNER, D_MODEL,
        D_MODEL, 2 * D_INNER, 2 * D_INNER);

    // 2) xc = silu(conv(x_e)+b), zs = silu(z)
    conv_silu_kernel<<<(NROWS * D_INNER + 255) / 256, 256>>>(conv_w, conv_b);

    // 3) xdbl = xc @ W_x               [2048,2048]@[2048,96]
    gemm_n96<<<dim3(3, NROWS / 8), dim3(32, 8)>>>(W_x);

    // 4) delta = softplus(xdbl[:, :64] @ W_dt + b_dt)   K=64, lda=96
    sgemm128<1><<<dim3(D_INNER / 128, NROWS / 128), 256>>>(
        xdbl, W_dt, b_dt, delta, NROWS, D_INNER, DT_RANK,
        XDBL_N, D_INNER, D_INNER);

    // 5) selective scan -> g_y (includes *silu(z) and +xc*D)
    scan_kernel<<<dim3(D_INNER / 16, B_SZ), 256>>>(A_log, Dp);

    // 6) out = y @ W_out               [2048,2048]@[2048,1024]
    sgemm128<0><<<dim3(D_MODEL / 128, NROWS / 128), 256>>>(
        ybuf, W_out, nullptr, out, NROWS, D_MODEL, D_INNER,
        D_INNER, D_MODEL, D_MODEL);
}

// round 4
// speedup vs baseline: 1.6503x; 1.2663x over previous
#include <cuda_runtime.h>
#include <cuda_bf16.h>
#include <math.h>
#include <stdint.h>

// ---------------- problem constants ----------------
#define D_MODEL 1024
#define D_STATE 16
#define D_CONV 4
#define D_INNER 2048
#define DT_RANK 64
#define B_SZ 2
#define SEQ 1024
#define NROWS (B_SZ * SEQ)              // 2048
#define XDBL_N (DT_RANK + 2 * D_STATE)  // 96

// ---------------- scratch (device globals; no allocation allowed) ----------
__device__ float g_xz[NROWS * 2 * D_INNER];     // 32 MB : [row, 4096] (x_e | z)
__device__ float g_xc[NROWS * D_INNER];         // 16 MB : silu(conv(x_e))
__device__ float g_zs[NROWS * D_INNER];         // 16 MB : silu(z)
__device__ float g_xdbl[NROWS * XDBL_N];        // 768 KB: [row, 96] = dt_r|B|C
__device__ float g_delta[NROWS * D_INNER];      // 16 MB : softplus(...)

// bf16 hi/lo splits for tensor-core GEMMs
__device__ __nv_bfloat16 g_xh[NROWS * D_MODEL];
__device__ __nv_bfloat16 g_xl[NROWS * D_MODEL];
__device__ __nv_bfloat16 g_winh[2 * D_INNER * D_MODEL]; // W_in^T [4096,1024]
__device__ __nv_bfloat16 g_winl[2 * D_INNER * D_MODEL];
__device__ __nv_bfloat16 g_yh[NROWS * D_INNER];
__device__ __nv_bfloat16 g_yl[NROWS * D_INNER];
__device__ __nv_bfloat16 g_woh[D_MODEL * D_INNER];      // W_out^T [1024,2048]
__device__ __nv_bfloat16 g_wol[D_MODEL * D_INNER];

// ======================= HMMA bf16 split GEMM ===============================
// C[M,N] (fp32) = (Ah+Al)[M,K] @ (Bh+Bl)^T, B* are [N,K] K-major, drop Al*Bl.
// CTA: 128x128 tile, 256 threads (8 warps, 2x4), warp tile 64x32.
// K chunk = 32, double-buffered smem, pitch 40 bf16 (80B, conflict-free).

#define APITCH 40                       // bf16 units per smem row
#define CHUNK_UNITS (128 * APITCH)      // one 128x32 tile in bf16 units
#define BUF_UNITS (4 * CHUNK_UNITS)     // Ah|Al|Bh|Bl

__device__ __forceinline__ void mma_bf16(float* c, const uint32_t* a, const uint32_t* b) {
    asm volatile(
        "mma.sync.aligned.m16n8k16.row.col.f32.bf16.bf16.f32 "
        "{%0,%1,%2,%3}, {%4,%5,%6,%7}, {%8,%9}, {%0,%1,%2,%3};"
        : "+f"(c[0]), "+f"(c[1]), "+f"(c[2]), "+f"(c[3])
        : "r"(a[0]), "r"(a[1]), "r"(a[2]), "r"(a[3]), "r"(b[0]), "r"(b[1]));
}

__global__ __launch_bounds__(256)
void hmma_gemm(const __nv_bfloat16* __restrict__ Ah, const __nv_bfloat16* __restrict__ Al,
               const __nv_bfloat16* __restrict__ Bh, const __nv_bfloat16* __restrict__ Bl,
               float* __restrict__ C, int K, int N)
{
    extern __shared__ __align__(16) __nv_bfloat16 s[];
    const int OAH = 0;
    const int OAL = CHUNK_UNITS;
    const int OBH = 2 * CHUNK_UNITS;
    const int OBL = 3 * CHUNK_UNITS;

    const int tid  = threadIdx.x;
    const int wid  = tid >> 5;
    const int lane = tid & 31;
    const int wm   = wid >> 2;   // 0..1 : 64 rows
    const int wn   = wid & 3;    // 0..3 : 32 cols

    const int brow = blockIdx.y * 128;
    const int bcol = blockIdx.x * 128;

    float acc[4][4][4];
#pragma unroll
    for (int i = 0; i < 4; i++)
#pragma unroll
        for (int j = 0; j < 4; j++)
#pragma unroll
            for (int q = 0; q < 4; q++) acc[i][j][q] = 0.f;

    const int nchunks = K >> 5;

    // loader: 512 uint4 per matrix-pair set; i -> row=i>>2, j16=i&3
#define LOAD_CHUNK(cidx, bufi)                                                  \
    {                                                                           \
        const int k0 = (cidx) << 5;                                             \
        __nv_bfloat16* base = s + (bufi) * BUF_UNITS;                           \
        _Pragma("unroll")                                                       \
        for (int i0 = 0; i0 < 2; i0++) {                                        \
            const int i = tid + i0 * 256;                                       \
            const int r = i >> 2, j = i & 3;                                    \
            const size_t ga = (size_t)(brow + r) * K + k0 + j * 8;              \
            const size_t gb = (size_t)(bcol + r) * K + k0 + j * 8;              \
            const int so = r * APITCH + j * 8;                                  \
            *(uint4*)(base + OAH + so) = *(const uint4*)(Ah + ga);              \
            *(uint4*)(base + OAL + so) = *(const uint4*)(Al + ga);              \
            *(uint4*)(base + OBH + so) = *(const uint4*)(Bh + gb);              \
            *(uint4*)(base + OBL + so) = *(const uint4*)(Bl + gb);              \
        }                                                                       \
    }

    const int frow = lane >> 2;          // 0..7
    const int fk   = (lane & 3) << 1;    // 0,2,4,6

#define COMPUTE_CHUNK(bufi)                                                     \
    {                                                                           \
        const __nv_bfloat16* base = s + (bufi) * BUF_UNITS;                     \
        _Pragma("unroll")                                                       \
        for (int step = 0; step < 2; step++) {                                  \
            const int kk = step << 4;                                           \
            uint32_t bh[4][2], bl[4][2];                                        \
            _Pragma("unroll")                                                   \
            for (int nt = 0; nt < 4; nt++) {                                    \
                const int nr = wn * 32 + nt * 8 + frow;                         \
                bh[nt][0] = *(const uint32_t*)(base + OBH + nr * APITCH + kk + fk);     \
                bh[nt][1] = *(const uint32_t*)(base + OBH + nr * APITCH + kk + fk + 8); \
                bl[nt][0] = *(const uint32_t*)(base + OBL + nr * APITCH + kk + fk);     \
                bl[nt][1] = *(const uint32_t*)(base + OBL + nr * APITCH + kk + fk + 8); \
            }                                                                   \
            _Pragma("unroll")                                                   \
            for (int mt = 0; mt < 4; mt++) {                                    \
                const int ar = wm * 64 + mt * 16 + frow;                        \
                uint32_t ah[4], al[4];                                          \
                ah[0] = *(const uint32_t*)(base + OAH + ar * APITCH + kk + fk);          \
                ah[1] = *(const uint32_t*)(base + OAH + (ar + 8) * APITCH + kk + fk);    \
                ah[2] = *(const uint32_t*)(base + OAH + ar * APITCH + kk + fk + 8);      \
                ah[3] = *(const uint32_t*)(base + OAH + (ar + 8) * APITCH + kk + fk + 8);\
                al[0] = *(const uint32_t*)(base + OAL + ar * APITCH + kk + fk);          \
                al[1] = *(const uint32_t*)(base + OAL + (ar + 8) * APITCH + kk + fk);    \
                al[2] = *(const uint32_t*)(base + OAL + ar * APITCH + kk + fk + 8);      \
                al[3] = *(const uint32_t*)(base + OAL + (ar + 8) * APITCH + kk + fk + 8);\
                _Pragma("unroll")                                               \
                for (int nt = 0; nt < 4; nt++) {                                \
                    mma_bf16(acc[mt][nt], ah, bh[nt]);                          \
                    mma_bf16(acc[mt][nt], ah, bl[nt]);                          \
                    mma_bf16(acc[mt][nt], al, bh[nt]);                          \
                }                                                               \
            }                                                                   \
        }                                                                       \
    }

    LOAD_CHUNK(0, 0);
    __syncthreads();
    for (int c = 0; c < nchunks; c++) {
        if (c + 1 < nchunks) LOAD_CHUNK(c + 1, (c + 1) & 1);
        COMPUTE_CHUNK(c & 1);
        __syncthreads();
    }

    // epilogue: c0,c1 -> (row, col..col+1); c2,c3 -> (row+8, ...)
#pragma unroll
    for (int mt = 0; mt < 4; mt++) {
        const int row = brow + wm * 64 + mt * 16 + frow;
#pragma unroll
        for (int nt = 0; nt < 4; nt++) {
            const int col = bcol + wn * 32 + nt * 8 + ((lane & 3) << 1);
            *(float2*)&C[(size_t)row * N + col] =
                make_float2(acc[mt][nt][0], acc[mt][nt][1]);
            *(float2*)&C[(size_t)(row + 8) * N + col] =
                make_float2(acc[mt][nt][2], acc[mt][nt][3]);
        }
    }
#undef LOAD_CHUNK
#undef COMPUTE_CHUNK
}

// ---------------- split helpers --------------------------------------------
__global__ __launch_bounds__(256)
void split_kernel(const float* __restrict__ src, __nv_bfloat16* __restrict__ hi,
                  __nv_bfloat16* __restrict__ lo, int n)
{
    int i = blockIdx.x * 256 + threadIdx.x;
    if (i >= n) return;
    float v = src[i];
    __nv_bfloat16 h = __float2bfloat16(v);
    hi[i] = h;
    lo[i] = __float2bfloat16(v - __bfloat162float(h));
}

// transpose + split: W[K,N] fp32 -> Th/Tl[N,K] bf16
__global__ __launch_bounds__(256)
void tsplit_kernel(const float* __restrict__ W, __nv_bfloat16* __restrict__ Th,
                   __nv_bfloat16* __restrict__ Tl, int K, int N)
{
    __shared__ float t[32][33];
    const int tx = threadIdx.x & 31;
    const int ty = threadIdx.x >> 5;      // 0..7
    const int n0 = blockIdx.x * 32;
    const int k0 = blockIdx.y * 32;
#pragma unroll
    for (int s = 0; s < 32; s += 8)
        t[ty + s][tx] = W[(size_t)(k0 + ty + s) * N + n0 + tx];
    __syncthreads();
#pragma unroll
    for (int s = 0; s < 32; s += 8) {
        float v = t[tx][ty + s];
        __nv_bfloat16 h = __float2bfloat16(v);
        const size_t o = (size_t)(n0 + ty + s) * K + k0 + tx;
        Th[o] = h;
        Tl[o] = __float2bfloat16(v - __bfloat162float(h));
    }
}

// ---------------- packed f32x2 helpers (FFMA2) ------------------------------
__device__ __forceinline__ unsigned long long pack_dup_f32(float x) {
    unsigned long long r;
    unsigned int u = __float_as_uint(x);
    asm("mov.b64 %0, {%1, %1};" : "=l"(r) : "r"(u));
    return r;
}
__device__ __forceinline__ unsigned long long fma_f32x2(
    unsigned long long a, unsigned long long b, unsigned long long c) {
    unsigned long long d;
    asm("fma.rn.f32x2 %0, %1, %2, %3;" : "=l"(d) : "l"(a), "l"(b), "l"(c));
    return d;
}
__device__ __forceinline__ float2 unpack_f32x2(unsigned long long v) {
    unsigned int lo, hi;
    asm("mov.b64 {%0, %1}, %2;" : "=r"(lo), "=r"(hi) : "l"(v));
    return make_float2(__uint_as_float(lo), __uint_as_float(hi));
}

// ---------------- FFMA2 GEMM (delta GEMM, K=64) -----------------------------
#define BK 16
template <int EPI>
__global__ __launch_bounds__(256, 2)
void sgemm128(const float* __restrict__ A, const float* __restrict__ B,
              const float* __restrict__ bias, float* __restrict__ C,
              int M, int N, int K, int lda, int ldb, int ldc)
{
    __shared__ __align__(16) float As[2][BK][128];
    __shared__ __align__(16) float Bs[2][BK][128];

    const int tid  = threadIdx.x;
    const int brow = blockIdx.y * 128;
    const int bcol = blockIdx.x * 128;

    const int arow = tid >> 1;
    const int acol = (tid & 1) << 3;
    const int bk = tid >> 4;
    const int bc = (tid & 15) << 3;
    const int tx = (tid & 15) << 3;
    const int ty = (tid >> 4) << 3;

    const float* Ap = A + (size_t)(brow + arow) * lda + acol;
    const float* Bp = B + (size_t)bk * ldb + bcol + bc;

    unsigned long long acc[8][4];
#pragma unroll
    for (int i = 0; i < 8; i++)
#pragma unroll
        for (int j = 0; j < 4; j++) acc[i][j] = 0ull;

    float4 a0 = *(const float4*)(Ap);
    float4 a1 = *(const float4*)(Ap + 4);
    float4 b0 = *(const float4*)(Bp);
    float4 b1 = *(const float4*)(Bp + 4);

#define STORE_TILE(bufi)                                            \
    {                                                               \
        As[bufi][acol + 0][arow] = a0.x;                            \
        As[bufi][acol + 1][arow] = a0.y;                            \
        As[bufi][acol + 2][arow] = a0.z;                            \
        As[bufi][acol + 3][arow] = a0.w;                            \
        As[bufi][acol + 4][arow] = a1.x;                            \
        As[bufi][acol + 5][arow] = a1.y;                            \
        As[bufi][acol + 6][arow] = a1.z;                            \
        As[bufi][acol + 7][arow] = a1.w;                            \
        *(float4*)&Bs[bufi][bk][bc]     = b0;                       \
        *(float4*)&Bs[bufi][bk][bc + 4] = b1;                       \
    }

#define COMPUTE_TILE(bufi)                                          \
    {                                                               \
        _Pragma("unroll")                                           \
        for (int kk = 0; kk < BK; kk++) {                           \
            float4 av0 = *(const float4*)&As[bufi][kk][ty];         \
            float4 av1 = *(const float4*)&As[bufi][kk][ty + 4];     \
            ulonglong2 bq01 = *(const ulonglong2*)&Bs[bufi][kk][tx];\
            ulonglong2 bq23 = *(const ulonglong2*)&Bs[bufi][kk][tx + 4];\
            unsigned long long bq[4] = {bq01.x, bq01.y, bq23.x, bq23.y};\
            float ar[8] = {av0.x, av0.y, av0.z, av0.w,              \
                           av1.x, av1.y, av1.z, av1.w};             \
            _Pragma("unroll")                                       \
            for (int i = 0; i < 8; i++) {                           \
                unsigned long long a2 = pack_dup_f32(ar[i]);        \
                _Pragma("unroll")                                   \
                for (int j = 0; j < 4; j++)                         \
                    acc[i][j] = fma_f32x2(a2, bq[j], acc[i][j]);    \
            }                                                       \
        }                                                           \
    }

    STORE_TILE(0);
    __syncthreads();

    int buf = 0;
    for (int k0 = BK; k0 < K; k0 += BK) {
        a0 = *(const float4*)(Ap + k0);
        a1 = *(const float4*)(Ap + k0 + 4);
        b0 = *(const float4*)(Bp + (size_t)k0 * ldb);
        b1 = *(const float4*)(Bp + (size_t)k0 * ldb + 4);
        COMPUTE_TILE(buf);
        STORE_TILE(buf ^ 1);
        __syncthreads();
        buf ^= 1;
    }
    COMPUTE_TILE(buf);

#pragma unroll
    for (int i = 0; i < 8; i++) {
        const int row = brow + ty + i;
#pragma unroll
        for (int j = 0; j < 4; j++) {
            float2 v = unpack_f32x2(acc[i][j]);
            const int col = bcol + tx + 2 * j;
            if (EPI == 1) {
                v.x += bias[col];
                v.y += bias[col + 1];
                v.x = (v.x > 20.f) ? v.x : log1pf(__expf(v.x));
                v.y = (v.y > 20.f) ? v.y : log1pf(__expf(v.y));
            }
            *(float2*)&C[(size_t)row * ldc + col] = v;
        }
    }
#undef STORE_TILE
#undef COMPUTE_TILE
}

// ---------- depthwise causal conv (k=4) + SiLU, plus silu(z) precompute ----
__global__ __launch_bounds__(256)
void conv_silu_kernel(const float* __restrict__ conv_w, const float* __restrict__ conv_b)
{
    int idx = blockIdx.x * blockDim.x + threadIdx.x;
    if (idx >= NROWS * D_INNER) return;
    const int d   = idx & (D_INNER - 1);
    const int row = idx >> 11;
    const int l   = row & (SEQ - 1);

    const float w0 = conv_w[d * 4 + 0];
    const float w1 = conv_w[d * 4 + 1];
    const float w2 = conv_w[d * 4 + 2];
    const float w3 = conv_w[d * 4 + 3];

    const float* xe = g_xz + (size_t)row * (2 * D_INNER) + d;
    float acc = conv_b[d];
    acc = fmaf(w3, xe[0], acc);
    if (l >= 1) acc = fmaf(w2, xe[-(2 * D_INNER)], acc);
    if (l >= 2) acc = fmaf(w1, xe[-2 * (2 * D_INNER)], acc);
    if (l >= 3) acc = fmaf(w0, xe[-3 * (2 * D_INNER)], acc);

    g_xc[idx] = acc / (1.f + __expf(-acc));

    const float zv = g_xz[(size_t)row * (2 * D_INNER) + D_INNER + d];
    g_zs[idx] = zv / (1.f + __expf(-zv));
}

// ---------- small-N GEMM: g_xdbl[2048,96] = g_xc @ W_x[2048,96] -------------
__global__ __launch_bounds__(256)
void gemm_n96(const float* __restrict__ Wx)
{
    __shared__ float Bs[64][32];
    const int tx  = threadIdx.x;
    const int ty  = threadIdx.y;
    const int tid = ty * 32 + tx;
    const int col = blockIdx.x * 32 + tx;
    const int row = blockIdx.y * 8 + ty;

    float acc = 0.f;
    const float* arow = g_xc + (size_t)row * D_INNER;

    for (int k0 = 0; k0 < D_INNER; k0 += 64) {
        for (int i = tid; i < 64 * 32; i += 256)
            Bs[i >> 5][i & 31] = Wx[(size_t)(k0 + (i >> 5)) * XDBL_N + blockIdx.x * 32 + (i & 31)];
        __syncthreads();
#pragma unroll
        for (int kk = 0; kk < 64; kk += 4) {
            float4 a4 = *(const float4*)(arow + k0 + kk);
            acc = fmaf(a4.x, Bs[kk + 0][tx], acc);
            acc = fmaf(a4.y, Bs[kk + 1][tx], acc);
            acc = fmaf(a4.z, Bs[kk + 2][tx], acc);
            acc = fmaf(a4.w, Bs[kk + 3][tx], acc);
        }
        __syncthreads();
    }
    if (col < XDBL_N) g_xdbl[(size_t)row * XDBL_N + col] = acc;
}

// ---------- selective scan: writes y directly as bf16 hi/lo split ----------
__global__ __launch_bounds__(256)
void scan_kernel(const float* __restrict__ A_log, const float* __restrict__ Dp)
{
    const int lane16 = threadIdx.x & 15;
    const int chan   = (blockIdx.x << 4) | (threadIdx.x >> 4);
    const int b      = blockIdx.y;

    const float Aval = -__expf(A_log[chan * D_STATE + lane16]);
    const float Dd   = Dp[chan];

    const float* dl = g_delta + (size_t)b * SEQ * D_INNER + chan;
    const float* xp = g_xc    + (size_t)b * SEQ * D_INNER + chan;
    const float* zp = g_zs    + (size_t)b * SEQ * D_INNER + chan;
    __nv_bfloat16* yh = g_yh  + (size_t)b * SEQ * D_INNER + chan;
    __nv_bfloat16* yl = g_yl  + (size_t)b * SEQ * D_INNER + chan;
    const float* bp = g_xdbl  + (size_t)b * SEQ * XDBL_N + DT_RANK + lane16;
    const float* cp = bp + D_STATE;

    float h = 0.f;
    for (int l = 0; l < SEQ; l += 4) {
        float dv[4], xv[4], Bn[4], Cn[4], zv[4], dA[4];
#pragma unroll
        for (int u = 0; u < 4; u++) {
            dv[u] = dl[u * D_INNER];
            xv[u] = xp[u * D_INNER];
            zv[u] = zp[u * D_INNER];
            Bn[u] = bp[u * XDBL_N];
            Cn[u] = cp[u * XDBL_N];
        }
#pragma unroll
        for (int u = 0; u < 4; u++)
            dA[u] = __expf(dv[u] * Aval);

        float contrib[4];
#pragma unroll
        for (int u = 0; u < 4; u++) {
            h = fmaf(dA[u], h, dv[u] * xv[u] * Bn[u]);
            contrib[u] = h * Cn[u];
        }
#pragma unroll
        for (int u = 0; u < 4; u++) {
            contrib[u] += __shfl_down_sync(0xffffffffu, contrib[u], 8, 16);
            contrib[u] += __shfl_down_sync(0xffffffffu, contrib[u], 4, 16);
            contrib[u] += __shfl_down_sync(0xffffffffu, contrib[u], 2, 16);
            contrib[u] += __shfl_down_sync(0xffffffffu, contrib[u], 1, 16);
        }
        if (lane16 == 0) {
#pragma unroll
            for (int u = 0; u < 4; u++) {
                float v = fmaf(xv[u], Dd, contrib[u]) * zv[u];
                __nv_bfloat16 hh = __float2bfloat16(v);
                yh[u * D_INNER] = hh;
                yl[u * D_INNER] = __float2bfloat16(v - __bfloat162float(hh));
            }
        }
        dl += 4 * D_INNER; xp += 4 * D_INNER; zp += 4 * D_INNER;
        yh += 4 * D_INNER; yl += 4 * D_INNER;
        bp += 4 * XDBL_N;  cp += 4 * XDBL_N;
    }
}

// ---------------- launch ----------------------------------------------------
extern "C" void kernel_launch(void* const* d_in, const int* in_sizes, int n_in,
                              void* d_out, int out_size)
{
    const float* x      = (const float*)d_in[0];
    const float* W_in   = (const float*)d_in[1];
    const float* conv_w = (const float*)d_in[2];
    const float* conv_b = (const float*)d_in[3];
    const float* W_x    = (const float*)d_in[4];
    const float* W_dt   = (const float*)d_in[5];
    const float* b_dt   = (const float*)d_in[6];
    const float* A_log  = (const float*)d_in[7];
    const float* Dp     = (const float*)d_in[8];
    const float* W_out  = (const float*)d_in[9];
    float* out = (float*)d_out;

    float *xz, *xdbl, *delta;
    __nv_bfloat16 *xh, *xl, *winh, *winl, *yh, *yl, *woh, *wol;
    cudaGetSymbolAddress((void**)&xz,    g_xz);
    cudaGetSymbolAddress((void**)&xdbl,  g_xdbl);
    cudaGetSymbolAddress((void**)&delta, g_delta);
    cudaGetSymbolAddress((void**)&xh,   g_xh);
    cudaGetSymbolAddress((void**)&xl,   g_xl);
    cudaGetSymbolAddress((void**)&winh, g_winh);
    cudaGetSymbolAddress((void**)&winl, g_winl);
    cudaGetSymbolAddress((void**)&yh,   g_yh);
    cudaGetSymbolAddress((void**)&yl,   g_yl);
    cudaGetSymbolAddress((void**)&woh,  g_woh);
    cudaGetSymbolAddress((void**)&wol,  g_wol);

    const int HSMEM = 2 * BUF_UNITS * (int)sizeof(__nv_bfloat16);  // 81920 B
    cudaFuncSetAttribute(hmma_gemm, cudaFuncAttributeMaxDynamicSharedMemorySize, HSMEM);

    // 0) bf16 splits of x and transposed weights
    split_kernel<<<(NROWS * D_MODEL + 255) / 256, 256>>>(x, xh, xl, NROWS * D_MODEL);
    tsplit_kernel<<<dim3(2 * D_INNER / 32, D_MODEL / 32), 256>>>(
        W_in, winh, winl, D_MODEL, 2 * D_INNER);
    tsplit_kernel<<<dim3(D_MODEL / 32, D_INNER / 32), 256>>>(
        W_out, woh, wol, D_INNER, D_MODEL);

    // 1) xz = x @ W_in   (HMMA split-bf16)   [2048,1024]@[1024,4096]
    hmma_gemm<<<dim3(2 * D_INNER / 128, NROWS / 128), 256, HSMEM>>>(
        xh, xl, winh, winl, xz, D_MODEL, 2 * D_INNER);

    // 2) xc = silu(conv(x_e)+b), zs = silu(z)
    conv_silu_kernel<<<(NROWS * D_INNER + 255) / 256, 256>>>(conv_w, conv_b);

    // 3) xdbl = xc @ W_x               [2048,2048]@[2048,96]
    gemm_n96<<<dim3(3, NROWS / 8), dim3(32, 8)>>>(W_x);

    // 4) delta = softplus(xdbl[:, :64] @ W_dt + b_dt)   K=64
    sgemm128<1><<<dim3(D_INNER / 128, NROWS / 128), 256>>>(
        xdbl, W_dt, b_dt, delta, NROWS, D_INNER, DT_RANK,
        XDBL_N, D_INNER, D_INNER);

    // 5) selective scan -> yh/yl bf16 split
    scan_kernel<<<dim3(D_INNER / 16, B_SZ), 256>>>(A_log, Dp);

    // 6) out = y @ W_out  (HMMA split-bf16)  [2048,2048]@[2048,1024]
    hmma_gemm<<<dim3(D_MODEL / 128, NROWS / 128), 256, HSMEM>>>(
        yh, yl, woh, wol, out, D_INNER, D_MODEL);
}

// round 5
// speedup vs baseline: 1.9303x; 1.1696x over previous
#include <cuda_runtime.h>
#include <cuda_bf16.h>
#include <math.h>
#include <stdint.h>

// ---------------- problem constants ----------------
#define D_MODEL 1024
#define D_STATE 16
#define D_CONV 4
#define D_INNER 2048
#define DT_RANK 64
#define B_SZ 2
#define SEQ 1024
#define NROWS (B_SZ * SEQ)              // 2048
#define XDBL_N (DT_RANK + 2 * D_STATE)  // 96

// ---------------- scratch (device globals; no allocation allowed) ----------
__device__ float g_xz[NROWS * 2 * D_INNER];
__device__ float g_xc[NROWS * D_INNER];
__device__ float g_zs[NROWS * D_INNER];
__device__ float g_xdbl[NROWS * XDBL_N];
__device__ float g_delta[NROWS * D_INNER];

__device__ __nv_bfloat16 g_xh[NROWS * D_MODEL];
__device__ __nv_bfloat16 g_xl[NROWS * D_MODEL];
__device__ __nv_bfloat16 g_winh[2 * D_INNER * D_MODEL]; // W_in^T [4096,1024]
__device__ __nv_bfloat16 g_winl[2 * D_INNER * D_MODEL];
__device__ __nv_bfloat16 g_yh[NROWS * D_INNER];
__device__ __nv_bfloat16 g_yl[NROWS * D_INNER];
__device__ __nv_bfloat16 g_woh[D_MODEL * D_INNER];      // W_out^T [1024,2048]
__device__ __nv_bfloat16 g_wol[D_MODEL * D_INNER];

// ======================= HMMA bf16 split GEMM ===============================
// C[M,N] fp32 = (Ah+Al)[M,K] @ (Bh+Bl)^T (B* [N,K] K-major), dropping Al*Bl.
// CTA 128x128, 8 warps (2x4), warp tile 64x32, K-chunk 32.
// smem: per buffer 4 tiles (Ah|Al|Bh|Bl) of 128x32 bf16, 64B pitch,
// XOR swizzle chunk = k16 ^ ((row>>1)&3)  -> ldmatrix & cp.async conflict-free.
// Double buffered: 2 * 32768 = 65536 B. cp.async pipeline.

#define TILE_BYTES 8192                  // 128*32*2
#define BUF_BYTES  32768                 // 4 tiles
#define OAL 8192
#define OBH 16384
#define OBL 24576

__device__ __forceinline__ uint32_t smem_u32(const void* p) {
    uint32_t a;
    asm("{ .reg .u64 t; cvta.to.shared.u64 t, %1; cvt.u32.u64 %0, t; }"
        : "=r"(a) : "l"(p));
    return a;
}

#define CP_ASYNC16(sa, gp) \
    asm volatile("cp.async.cg.shared.global [%0], [%1], 16;" :: "r"(sa), "l"(gp))
#define CP_COMMIT() asm volatile("cp.async.commit_group;")
#define CP_WAIT1()  asm volatile("cp.async.wait_group 1;")
#define CP_WAIT0()  asm volatile("cp.async.wait_group 0;")

#define LDX4(r0, r1, r2, r3, a)                                                  \
    asm volatile("ldmatrix.sync.aligned.m8n8.x4.shared.b16 {%0,%1,%2,%3}, [%4];" \
                 : "=r"(r0), "=r"(r1), "=r"(r2), "=r"(r3) : "r"(a))

__device__ __forceinline__ void mma_bf16(float* c, const uint32_t* a, const uint32_t* b) {
    asm volatile(
        "mma.sync.aligned.m16n8k16.row.col.f32.bf16.bf16.f32 "
        "{%0,%1,%2,%3}, {%4,%5,%6,%7}, {%8,%9}, {%0,%1,%2,%3};"
        : "+f"(c[0]), "+f"(c[1]), "+f"(c[2]), "+f"(c[3])
        : "r"(a[0]), "r"(a[1]), "r"(a[2]), "r"(a[3]), "r"(b[0]), "r"(b[1]));
}

__global__ __launch_bounds__(256, 2)
void hmma_gemm(const __nv_bfloat16* __restrict__ Ah, const __nv_bfloat16* __restrict__ Al,
               const __nv_bfloat16* __restrict__ Bh, const __nv_bfloat16* __restrict__ Bl,
               float* __restrict__ C, int K, int N)
{
    extern __shared__ __align__(128) char s[];
    const uint32_t sb = smem_u32(s);

    const int tid  = threadIdx.x;
    const int wid  = tid >> 5;
    const int lane = tid & 31;
    const int wm   = wid >> 2;   // 0..1 : 64-row block
    const int wn   = wid & 3;    // 0..3 : 32-col block

    const int brow = blockIdx.y * 128;
    const int bcol = blockIdx.x * 128;

    float acc[4][4][4];
#pragma unroll
    for (int i = 0; i < 4; i++)
#pragma unroll
        for (int j = 0; j < 4; j++)
#pragma unroll
            for (int q = 0; q < 4; q++) acc[i][j][q] = 0.f;

    // ---- loader indices: i in [0,512): r=i>>2 (row), k16=i&3 (16B chunk)
    const int l_r0 = tid >> 2;
    const int l_k  = tid & 3;

#define LOAD_CHUNK(cidx, bufi)                                                    \
    {                                                                             \
        const int k0 = (cidx) << 5;                                               \
        const uint32_t bbase = sb + (bufi) * BUF_BYTES;                           \
        _Pragma("unroll")                                                         \
        for (int i0 = 0; i0 < 2; i0++) {                                          \
            const int r = l_r0 + i0 * 64;                                         \
            const uint32_t so = (uint32_t)(r * 64 + ((l_k ^ ((r >> 1) & 3)) << 4)); \
            const size_t ga = (size_t)(brow + r) * K + k0 + l_k * 8;              \
            const size_t gb = (size_t)(bcol + r) * K + k0 + l_k * 8;              \
            CP_ASYNC16(bbase + so,        Ah + ga);                               \
            CP_ASYNC16(bbase + OAL + so,  Al + ga);                               \
            CP_ASYNC16(bbase + OBH + so,  Bh + gb);                               \
            CP_ASYNC16(bbase + OBL + so,  Bl + gb);                               \
        }                                                                         \
    }

    // ---- per-thread ldmatrix base offsets (relative to buffer start)
    const int g  = lane >> 3;       // x4 lane group
    const int li = lane & 7;
    const int swz = (li >> 1) & 3;
    // A: groups (g&1)->+8 rows, (g>>1)->k-half
    const int rowA = wm * 64 + li + (g & 1) * 8;
    const int khA  = g >> 1;
    // B: groups (g>>1)->+8 n-rows, (g&1)->k-half
    const int rowB = wn * 32 + li + (g >> 1) * 8;
    const int khB  = g & 1;
    uint32_t aoffs[2], boffs[2];
#pragma unroll
    for (int sN = 0; sN < 2; sN++) {
        aoffs[sN] = (uint32_t)(rowA * 64 + (((2 * sN + khA) ^ swz) << 4));
        boffs[sN] = (uint32_t)(OBH + rowB * 64 + (((2 * sN + khB) ^ swz) << 4));
    }

#define COMPUTE_STEP(sidx, bofs)                                                  \
    {                                                                             \
        const uint32_t aA = sb + (bofs) + aoffs[sidx];                            \
        const uint32_t bB = sb + (bofs) + boffs[sidx];                            \
        uint32_t bh[4][2], bl[4][2];                                              \
        LDX4(bh[0][0], bh[0][1], bh[1][0], bh[1][1], bB);                         \
        LDX4(bh[2][0], bh[2][1], bh[3][0], bh[3][1], bB + 1024);                  \
        LDX4(bl[0][0], bl[0][1], bl[1][0], bl[1][1], bB + 8192);                  \
        LDX4(bl[2][0], bl[2][1], bl[3][0], bl[3][1], bB + 8192 + 1024);           \
        _Pragma("unroll")                                                         \
        for (int half = 0; half < 2; half++) {                                    \
            uint32_t ah[2][4], al[2][4];                                          \
            const uint32_t ab = aA + half * 2048;                                 \
            LDX4(ah[0][0], ah[0][1], ah[0][2], ah[0][3], ab);                     \
            LDX4(ah[1][0], ah[1][1], ah[1][2], ah[1][3], ab + 1024);              \
            LDX4(al[0][0], al[0][1], al[0][2], al[0][3], ab + OAL);               \
            LDX4(al[1][0], al[1][1], al[1][2], al[1][3], ab + OAL + 1024);        \
            _Pragma("unroll")                                                     \
            for (int m2 = 0; m2 < 2; m2++)                                        \
                _Pragma("unroll")                                                 \
                for (int nt = 0; nt < 4; nt++)                                    \
                    mma_bf16(acc[half * 2 + m2][nt], ah[m2], bh[nt]);             \
            _Pragma("unroll")                                                     \
            for (int m2 = 0; m2 < 2; m2++)                                        \
                _Pragma("unroll")                                                 \
                for (int nt = 0; nt < 4; nt++)                                    \
                    mma_bf16(acc[half * 2 + m2][nt], ah[m2], bl[nt]);             \
            _Pragma("unroll")                                                     \
            for (int m2 = 0; m2 < 2; m2++)                                        \
                _Pragma("unroll")                                                 \
                for (int nt = 0; nt < 4; nt++)                                    \
                    mma_bf16(acc[half * 2 + m2][nt], al[m2], bh[nt]);             \
        }                                                                         \
    }

    const int nchunks = K >> 5;
    LOAD_CHUNK(0, 0);
    CP_COMMIT();

    for (int c = 0; c < nchunks; c++) {
        if (c + 1 < nchunks) {
            LOAD_CHUNK(c + 1, (c + 1) & 1);
            CP_COMMIT();
            CP_WAIT1();
        } else {
            CP_WAIT0();
        }
        __syncthreads();
        const uint32_t bofs = (uint32_t)((c & 1) * BUF_BYTES);
        COMPUTE_STEP(0, bofs);
        COMPUTE_STEP(1, bofs);
        __syncthreads();
    }

    // ---- epilogue
    const int frow = lane >> 2;
    const int fcol = (lane & 3) << 1;
#pragma unroll
    for (int mt = 0; mt < 4; mt++) {
        const int row = brow + wm * 64 + mt * 16 + frow;
#pragma unroll
        for (int nt = 0; nt < 4; nt++) {
            const int col = bcol + wn * 32 + nt * 8 + fcol;
            *(float2*)&C[(size_t)row * N + col] =
                make_float2(acc[mt][nt][0], acc[mt][nt][1]);
            *(float2*)&C[(size_t)(row + 8) * N + col] =
                make_float2(acc[mt][nt][2], acc[mt][nt][3]);
        }
    }
#undef LOAD_CHUNK
#undef COMPUTE_STEP
}

// ---------------- split helpers --------------------------------------------
__global__ __launch_bounds__(256)
void split_kernel(const float* __restrict__ src, __nv_bfloat16* __restrict__ hi,
                  __nv_bfloat16* __restrict__ lo, int n)
{
    int i = blockIdx.x * 256 + threadIdx.x;
    if (i >= n) return;
    float v = src[i];
    __nv_bfloat16 h = __float2bfloat16(v);
    hi[i] = h;
    lo[i] = __float2bfloat16(v - __bfloat162float(h));
}

// transpose + split: W[K,N] fp32 -> Th/Tl[N,K] bf16
__global__ __launch_bounds__(256)
void tsplit_kernel(const float* __restrict__ W, __nv_bfloat16* __restrict__ Th,
                   __nv_bfloat16* __restrict__ Tl, int K, int N)
{
    __shared__ float t[32][33];
    const int tx = threadIdx.x & 31;
    const int ty = threadIdx.x >> 5;
    const int n0 = blockIdx.x * 32;
    const int k0 = blockIdx.y * 32;
#pragma unroll
    for (int s2 = 0; s2 < 32; s2 += 8)
        t[ty + s2][tx] = W[(size_t)(k0 + ty + s2) * N + n0 + tx];
    __syncthreads();
#pragma unroll
    for (int s2 = 0; s2 < 32; s2 += 8) {
        float v = t[tx][ty + s2];
        __nv_bfloat16 h = __float2bfloat16(v);
        const size_t o = (size_t)(n0 + ty + s2) * K + k0 + tx;
        Th[o] = h;
        Tl[o] = __float2bfloat16(v - __bfloat162float(h));
    }
}

// ---------------- packed f32x2 helpers (FFMA2) ------------------------------
__device__ __forceinline__ unsigned long long pack_dup_f32(float x) {
    unsigned long long r;
    unsigned int u = __float_as_uint(x);
    asm("mov.b64 %0, {%1, %1};" : "=l"(r) : "r"(u));
    return r;
}
__device__ __forceinline__ unsigned long long fma_f32x2(
    unsigned long long a, unsigned long long b, unsigned long long c) {
    unsigned long long d;
    asm("fma.rn.f32x2 %0, %1, %2, %3;" : "=l"(d) : "l"(a), "l"(b), "l"(c));
    return d;
}
__device__ __forceinline__ float2 unpack_f32x2(unsigned long long v) {
    unsigned int lo, hi;
    asm("mov.b64 {%0, %1}, %2;" : "=r"(lo), "=r"(hi) : "l"(v));
    return make_float2(__uint_as_float(lo), __uint_as_float(hi));
}

// ---------------- FFMA2 GEMM (delta GEMM, K=64) -----------------------------
#define BK 16
template <int EPI>
__global__ __launch_bounds__(256, 2)
void sgemm128(const float* __restrict__ A, const float* __restrict__ B,
              const float* __restrict__ bias, float* __restrict__ C,
              int M, int N, int K, int lda, int ldb, int ldc)
{
    __shared__ __align__(16) float As[2][BK][128];
    __shared__ __align__(16) float Bs[2][BK][128];

    const int tid  = threadIdx.x;
    const int brow = blockIdx.y * 128;
    const int bcol = blockIdx.x * 128;

    const int arow = tid >> 1;
    const int acol = (tid & 1) << 3;
    const int bk = tid >> 4;
    const int bc = (tid & 15) << 3;
    const int tx = (tid & 15) << 3;
    const int ty = (tid >> 4) << 3;

    const float* Ap = A + (size_t)(brow + arow) * lda + acol;
    const float* Bp = B + (size_t)bk * ldb + bcol + bc;

    unsigned long long acc[8][4];
#pragma unroll
    for (int i = 0; i < 8; i++)
#pragma unroll
        for (int j = 0; j < 4; j++) acc[i][j] = 0ull;

    float4 a0 = *(const float4*)(Ap);
    float4 a1 = *(const float4*)(Ap + 4);
    float4 b0 = *(const float4*)(Bp);
    float4 b1 = *(const float4*)(Bp + 4);

#define STORE_TILE(bufi)                                            \
    {                                                               \
        As[bufi][acol + 0][arow] = a0.x;                            \
        As[bufi][acol + 1][arow] = a0.y;                            \
        As[bufi][acol + 2][arow] = a0.z;                            \
        As[bufi][acol + 3][arow] = a0.w;                            \
        As[bufi][acol + 4][arow] = a1.x;                            \
        As[bufi][acol + 5][arow] = a1.y;                            \
        As[bufi][acol + 6][arow] = a1.z;                            \
        As[bufi][acol + 7][arow] = a1.w;                            \
        *(float4*)&Bs[bufi][bk][bc]     = b0;                       \
        *(float4*)&Bs[bufi][bk][bc + 4] = b1;                       \
    }

#define COMPUTE_TILE(bufi)                                          \
    {                                                               \
        _Pragma("unroll")                                           \
        for (int kk = 0; kk < BK; kk++) {                           \
            float4 av0 = *(const float4*)&As[bufi][kk][ty];         \
            float4 av1 = *(const float4*)&As[bufi][kk][ty + 4];     \
            ulonglong2 bq01 = *(const ulonglong2*)&Bs[bufi][kk][tx];\
            ulonglong2 bq23 = *(const ulonglong2*)&Bs[bufi][kk][tx + 4];\
            unsigned long long bq[4] = {bq01.x, bq01.y, bq23.x, bq23.y};\
            float ar[8] = {av0.x, av0.y, av0.z, av0.w,              \
                           av1.x, av1.y, av1.z, av1.w};             \
            _Pragma("unroll")                                       \
            for (int i = 0; i < 8; i++) {                           \
                unsigned long long a2 = pack_dup_f32(ar[i]);        \
                _Pragma("unroll")                                   \
                for (int j = 0; j < 4; j++)                         \
                    acc[i][j] = fma_f32x2(a2, bq[j], acc[i][j]);    \
            }                                                       \
        }                                                           \
    }

    STORE_TILE(0);
    __syncthreads();

    int buf = 0;
    for (int k0 = BK; k0 < K; k0 += BK) {
        a0 = *(const float4*)(Ap + k0);
        a1 = *(const float4*)(Ap + k0 + 4);
        b0 = *(const float4*)(Bp + (size_t)k0 * ldb);
        b1 = *(const float4*)(Bp + (size_t)k0 * ldb + 4);
        COMPUTE_TILE(buf);
        STORE_TILE(buf ^ 1);
        __syncthreads();
        buf ^= 1;
    }
    COMPUTE_TILE(buf);

#pragma unroll
    for (int i = 0; i < 8; i++) {
        const int row = brow + ty + i;
#pragma unroll
        for (int j = 0; j < 4; j++) {
            float2 v = unpack_f32x2(acc[i][j]);
            const int col = bcol + tx + 2 * j;
            if (EPI == 1) {
                v.x += bias[col];
                v.y += bias[col + 1];
                v.x = (v.x > 20.f) ? v.x : log1pf(__expf(v.x));
                v.y = (v.y > 20.f) ? v.y : log1pf(__expf(v.y));
            }
            *(float2*)&C[(size_t)row * ldc + col] = v;
        }
    }
#undef STORE_TILE
#undef COMPUTE_TILE
}

// ---------- depthwise causal conv (k=4) + SiLU, plus silu(z) precompute ----
__global__ __launch_bounds__(256)
void conv_silu_kernel(const float* __restrict__ conv_w, const float* __restrict__ conv_b)
{
    int idx = blockIdx.x * blockDim.x + threadIdx.x;
    if (idx >= NROWS * D_INNER) return;
    const int d   = idx & (D_INNER - 1);
    const int row = idx >> 11;
    const int l   = row & (SEQ - 1);

    const float w0 = conv_w[d * 4 + 0];
    const float w1 = conv_w[d * 4 + 1];
    const float w2 = conv_w[d * 4 + 2];
    const float w3 = conv_w[d * 4 + 3];

    const float* xe = g_xz + (size_t)row * (2 * D_INNER) + d;
    float acc = conv_b[d];
    acc = fmaf(w3, xe[0], acc);
    if (l >= 1) acc = fmaf(w2, xe[-(2 * D_INNER)], acc);
    if (l >= 2) acc = fmaf(w1, xe[-2 * (2 * D_INNER)], acc);
    if (l >= 3) acc = fmaf(w0, xe[-3 * (2 * D_INNER)], acc);

    g_xc[idx] = acc / (1.f + __expf(-acc));

    const float zv = g_xz[(size_t)row * (2 * D_INNER) + D_INNER + d];
    g_zs[idx] = zv / (1.f + __expf(-zv));
}

// ---------- small-N GEMM: g_xdbl[2048,96] = g_xc @ W_x[2048,96] -------------
__global__ __launch_bounds__(256)
void gemm_n96(const float* __restrict__ Wx)
{
    __shared__ float Bs[64][32];
    const int tx  = threadIdx.x;
    const int ty  = threadIdx.y;
    const int tid = ty * 32 + tx;
    const int col = blockIdx.x * 32 + tx;
    const int row = blockIdx.y * 8 + ty;

    float acc = 0.f;
    const float* arow = g_xc + (size_t)row * D_INNER;

    for (int k0 = 0; k0 < D_INNER; k0 += 64) {
        for (int i = tid; i < 64 * 32; i += 256)
            Bs[i >> 5][i & 31] = Wx[(size_t)(k0 + (i >> 5)) * XDBL_N + blockIdx.x * 32 + (i & 31)];
        __syncthreads();
#pragma unroll
        for (int kk = 0; kk < 64; kk += 4) {
            float4 a4 = *(const float4*)(arow + k0 + kk);
            acc = fmaf(a4.x, Bs[kk + 0][tx], acc);
            acc = fmaf(a4.y, Bs[kk + 1][tx], acc);
            acc = fmaf(a4.z, Bs[kk + 2][tx], acc);
            acc = fmaf(a4.w, Bs[kk + 3][tx], acc);
        }
        __syncthreads();
    }
    if (col < XDBL_N) g_xdbl[(size_t)row * XDBL_N + col] = acc;
}

// ---------- selective scan: writes y directly as bf16 hi/lo split ----------
__global__ __launch_bounds__(256)
void scan_kernel(const float* __restrict__ A_log, const float* __restrict__ Dp)
{
    const int lane16 = threadIdx.x & 15;
    const int chan   = (blockIdx.x << 4) | (threadIdx.x >> 4);
    const int b      = blockIdx.y;

    const float Aval = -__expf(A_log[chan * D_STATE + lane16]);
    const float Dd   = Dp[chan];

    const float* dl = g_delta + (size_t)b * SEQ * D_INNER + chan;
    const float* xp = g_xc    + (size_t)b * SEQ * D_INNER + chan;
    const float* zp = g_zs    + (size_t)b * SEQ * D_INNER + chan;
    __nv_bfloat16* yh = g_yh  + (size_t)b * SEQ * D_INNER + chan;
    __nv_bfloat16* yl = g_yl  + (size_t)b * SEQ * D_INNER + chan;
    const float* bp = g_xdbl  + (size_t)b * SEQ * XDBL_N + DT_RANK + lane16;
    const float* cp = bp + D_STATE;

    float h = 0.f;
    for (int l = 0; l < SEQ; l += 4) {
        float dv[4], xv[4], Bn[4], Cn[4], zv[4], dA[4];
#pragma unroll
        for (int u = 0; u < 4; u++) {
            dv[u] = dl[u * D_INNER];
            xv[u] = xp[u * D_INNER];
            zv[u] = zp[u * D_INNER];
            Bn[u] = bp[u * XDBL_N];
            Cn[u] = cp[u * XDBL_N];
        }
#pragma unroll
        for (int u = 0; u < 4; u++)
            dA[u] = __expf(dv[u] * Aval);

        float contrib[4];
#pragma unroll
        for (int u = 0; u < 4; u++) {
            h = fmaf(dA[u], h, dv[u] * xv[u] * Bn[u]);
            contrib[u] = h * Cn[u];
        }
#pragma unroll
        for (int u = 0; u < 4; u++) {
            contrib[u] += __shfl_down_sync(0xffffffffu, contrib[u], 8, 16);
            contrib[u] += __shfl_down_sync(0xffffffffu, contrib[u], 4, 16);
            contrib[u] += __shfl_down_sync(0xffffffffu, contrib[u], 2, 16);
            contrib[u] += __shfl_down_sync(0xffffffffu, contrib[u], 1, 16);
        }
        if (lane16 == 0) {
#pragma unroll
            for (int u = 0; u < 4; u++) {
                float v = fmaf(xv[u], Dd, contrib[u]) * zv[u];
                __nv_bfloat16 hh = __float2bfloat16(v);
                yh[u * D_INNER] = hh;
                yl[u * D_INNER] = __float2bfloat16(v - __bfloat162float(hh));
            }
        }
        dl += 4 * D_INNER; xp += 4 * D_INNER; zp += 4 * D_INNER;
        yh += 4 * D_INNER; yl += 4 * D_INNER;
        bp += 4 * XDBL_N;  cp += 4 * XDBL_N;
    }
}

// ---------------- launch ----------------------------------------------------
extern "C" void kernel_launch(void* const* d_in, const int* in_sizes, int n_in,
                              void* d_out, int out_size)
{
    const float* x      = (const float*)d_in[0];
    const float* W_in   = (const float*)d_in[1];
    const float* conv_w = (const float*)d_in[2];
    const float* conv_b = (const float*)d_in[3];
    const float* W_x    = (const float*)d_in[4];
    const float* W_dt   = (const float*)d_in[5];
    const float* b_dt   = (const float*)d_in[6];
    const float* A_log  = (const float*)d_in[7];
    const float* Dp     = (const float*)d_in[8];
    const float* W_out  = (const float*)d_in[9];
    float* out = (float*)d_out;

    float *xz, *xdbl, *delta;
    __nv_bfloat16 *xh, *xl, *winh, *winl, *yh, *yl, *woh, *wol;
    cudaGetSymbolAddress((void**)&xz,    g_xz);
    cudaGetSymbolAddress((void**)&xdbl,  g_xdbl);
    cudaGetSymbolAddress((void**)&delta, g_delta);
    cudaGetSymbolAddress((void**)&xh,   g_xh);
    cudaGetSymbolAddress((void**)&xl,   g_xl);
    cudaGetSymbolAddress((void**)&winh, g_winh);
    cudaGetSymbolAddress((void**)&winl, g_winl);
    cudaGetSymbolAddress((void**)&yh,   g_yh);
    cudaGetSymbolAddress((void**)&yl,   g_yl);
    cudaGetSymbolAddress((void**)&woh,  g_woh);
    cudaGetSymbolAddress((void**)&wol,  g_wol);

    const int HSMEM = 2 * BUF_BYTES;  // 65536
    cudaFuncSetAttribute(hmma_gemm, cudaFuncAttributeMaxDynamicSharedMemorySize, HSMEM);

    // 0) bf16 splits of x and transposed weights
    split_kernel<<<(NROWS * D_MODEL + 255) / 256, 256>>>(x, xh, xl, NROWS * D_MODEL);
    tsplit_kernel<<<dim3(2 * D_INNER / 32, D_MODEL / 32), 256>>>(
        W_in, winh, winl, D_MODEL, 2 * D_INNER);
    tsplit_kernel<<<dim3(D_MODEL / 32, D_INNER / 32), 256>>>(
        W_out, woh, wol, D_INNER, D_MODEL);

    // 1) xz = x @ W_in   (HMMA split-bf16)   [2048,1024]@[1024,4096]
    hmma_gemm<<<dim3(2 * D_INNER / 128, NROWS / 128), 256, HSMEM>>>(
        xh, xl, winh, winl, xz, D_MODEL, 2 * D_INNER);

    // 2) xc = silu(conv(x_e)+b), zs = silu(z)
    conv_silu_kernel<<<(NROWS * D_INNER + 255) / 256, 256>>>(conv_w, conv_b);

    // 3) xdbl = xc @ W_x               [2048,2048]@[2048,96]
    gemm_n96<<<dim3(3, NROWS / 8), dim3(32, 8)>>>(W_x);

    // 4) delta = softplus(xdbl[:, :64] @ W_dt + b_dt)   K=64
    sgemm128<1><<<dim3(D_INNER / 128, NROWS / 128), 256>>>(
        xdbl, W_dt, b_dt, delta, NROWS, D_INNER, DT_RANK,
        XDBL_N, D_INNER, D_INNER);

    // 5) selective scan -> yh/yl bf16 split
    scan_kernel<<<dim3(D_INNER / 16, B_SZ), 256>>>(A_log, Dp);

    // 6) out = y @ W_out  (HMMA split-bf16)  [2048,2048]@[2048,1024]
    hmma_gemm<<<dim3(D_MODEL / 128, NROWS / 128), 256, HSMEM>>>(
        yh, yl, woh, wol, out, D_INNER, D_MODEL);
}

// round 6
// speedup vs baseline: 2.6801x; 1.3885x over previous
#include <cuda_runtime.h>
#include <cuda_bf16.h>
#include <math.h>
#include <stdint.h>

// ---------------- problem constants ----------------
#define D_MODEL 1024
#define D_STATE 16
#define D_CONV 4
#define D_INNER 2048
#define DT_RANK 64
#define B_SZ 2
#define SEQ 1024
#define NROWS (B_SZ * SEQ)              // 2048
#define XDBL_N (DT_RANK + 2 * D_STATE)  // 96

// ---------------- scratch (device globals; no allocation allowed) ----------
__device__ float g_xz[NROWS * 2 * D_INNER];
__device__ float g_xc[NROWS * D_INNER];
__device__ float g_zs[NROWS * D_INNER];
__device__ float g_xdbl[NROWS * XDBL_N];
__device__ float g_delta[NROWS * D_INNER];
__device__ float g_part[4 * NROWS * D_MODEL];           // split-K partials (32MB)

__device__ __nv_bfloat16 g_xh[NROWS * D_MODEL];
__device__ __nv_bfloat16 g_xl[NROWS * D_MODEL];
__device__ __nv_bfloat16 g_winh[2 * D_INNER * D_MODEL]; // W_in^T [4096,1024]
__device__ __nv_bfloat16 g_winl[2 * D_INNER * D_MODEL];
__device__ __nv_bfloat16 g_yh[NROWS * D_INNER];
__device__ __nv_bfloat16 g_yl[NROWS * D_INNER];
__device__ __nv_bfloat16 g_woh[D_MODEL * D_INNER];      // W_out^T [1024,2048]
__device__ __nv_bfloat16 g_wol[D_MODEL * D_INNER];

// ======================= HMMA bf16 split GEMM ===============================
// C[M,N] fp32 = (Ah+Al)[M,K] @ (Bh+Bl)^T (B* [N,K] K-major), dropping Al*Bl.
// CTA 128x128, 8 warps (2x4), warp tile 64x32, K-chunk 32.
// 3-stage cp.async pipeline, ONE __syncthreads per chunk.
// blockIdx.z = split-K partition; each writes its own C slab of M*N.

#define BUF_BYTES  32768                 // 4 tiles of 128x32 bf16
#define OAL 8192
#define OBH 16384
#define OBL 24576

__device__ __forceinline__ uint32_t smem_u32(const void* p) {
    uint32_t a;
    asm("{ .reg .u64 t; cvta.to.shared.u64 t, %1; cvt.u32.u64 %0, t; }"
        : "=r"(a) : "l"(p));
    return a;
}

#define CP_ASYNC16(sa, gp) \
    asm volatile("cp.async.cg.shared.global [%0], [%1], 16;" :: "r"(sa), "l"(gp))
#define CP_COMMIT() asm volatile("cp.async.commit_group;")
#define CP_WAIT1()  asm volatile("cp.async.wait_group 1;")

#define LDX4(r0, r1, r2, r3, a)                                                  \
    asm volatile("ldmatrix.sync.aligned.m8n8.x4.shared.b16 {%0,%1,%2,%3}, [%4];" \
                 : "=r"(r0), "=r"(r1), "=r"(r2), "=r"(r3) : "r"(a))

__device__ __forceinline__ void mma_bf16(float* c, const uint32_t* a, const uint32_t* b) {
    asm volatile(
        "mma.sync.aligned.m16n8k16.row.col.f32.bf16.bf16.f32 "
        "{%0,%1,%2,%3}, {%4,%5,%6,%7}, {%8,%9}, {%0,%1,%2,%3};"
        : "+f"(c[0]), "+f"(c[1]), "+f"(c[2]), "+f"(c[3])
        : "r"(a[0]), "r"(a[1]), "r"(a[2]), "r"(a[3]), "r"(b[0]), "r"(b[1]));
}

__global__ __launch_bounds__(256, 2)
void hmma_gemm(const __nv_bfloat16* __restrict__ Ah, const __nv_bfloat16* __restrict__ Al,
               const __nv_bfloat16* __restrict__ Bh, const __nv_bfloat16* __restrict__ Bl,
               float* __restrict__ C, int K, int N, int Kpart)
{
    extern __shared__ __align__(128) char s[];
    const uint32_t sb = smem_u32(s);

    const int tid  = threadIdx.x;
    const int wid  = tid >> 5;
    const int lane = tid & 31;
    const int wm   = wid >> 2;
    const int wn   = wid & 3;

    const int brow  = blockIdx.y * 128;
    const int bcol  = blockIdx.x * 128;
    const int kbase = blockIdx.z * Kpart;
    C += (size_t)blockIdx.z * (size_t)(gridDim.y * 128) * N;

    float acc[4][4][4];
#pragma unroll
    for (int i = 0; i < 4; i++)
#pragma unroll
        for (int j = 0; j < 4; j++)
#pragma unroll
            for (int q = 0; q < 4; q++) acc[i][j][q] = 0.f;

    const int l_r0 = tid >> 2;
    const int l_k  = tid & 3;

#define LOAD_CHUNK(cidx, bufi)                                                    \
    {                                                                             \
        const int k0 = kbase + ((cidx) << 5);                                     \
        const uint32_t bbase = sb + (bufi) * BUF_BYTES;                           \
        _Pragma("unroll")                                                         \
        for (int i0 = 0; i0 < 2; i0++) {                                          \
            const int r = l_r0 + i0 * 64;                                         \
            const uint32_t so = (uint32_t)(r * 64 + ((l_k ^ ((r >> 1) & 3)) << 4)); \
            const size_t ga = (size_t)(brow + r) * K + k0 + l_k * 8;              \
            const size_t gb = (size_t)(bcol + r) * K + k0 + l_k * 8;              \
            CP_ASYNC16(bbase + so,        Ah + ga);                               \
            CP_ASYNC16(bbase + OAL + so,  Al + ga);                               \
            CP_ASYNC16(bbase + OBH + so,  Bh + gb);                               \
            CP_ASYNC16(bbase + OBL + so,  Bl + gb);                               \
        }                                                                         \
    }

    const int g  = lane >> 3;
    const int li = lane & 7;
    const int swz = (li >> 1) & 3;
    const int rowA = wm * 64 + li + (g & 1) * 8;
    const int khA  = g >> 1;
    const int rowB = wn * 32 + li + (g >> 1) * 8;
    const int khB  = g & 1;
    uint32_t aoffs[2], boffs[2];
#pragma unroll
    for (int sN = 0; sN < 2; sN++) {
        aoffs[sN] = (uint32_t)(rowA * 64 + (((2 * sN + khA) ^ swz) << 4));
        boffs[sN] = (uint32_t)(OBH + rowB * 64 + (((2 * sN + khB) ^ swz) << 4));
    }

#define COMPUTE_STEP(sidx, bofs)                                                  \
    {                                                                             \
        const uint32_t aA = sb + (bofs) + aoffs[sidx];                            \
        const uint32_t bB = sb + (bofs) + boffs[sidx];                            \
        uint32_t bh[4][2], bl[4][2];                                              \
        LDX4(bh[0][0], bh[0][1], bh[1][0], bh[1][1], bB);                         \
        LDX4(bh[2][0], bh[2][1], bh[3][0], bh[3][1], bB + 1024);                  \
        LDX4(bl[0][0], bl[0][1], bl[1][0], bl[1][1], bB + 8192);                  \
        LDX4(bl[2][0], bl[2][1], bl[3][0], bl[3][1], bB + 8192 + 1024);           \
        _Pragma("unroll")                                                         \
        for (int half = 0; half < 2; half++) {                                    \
            uint32_t ah[2][4], al[2][4];                                          \
            const uint32_t ab = aA + half * 2048;                                 \
            LDX4(ah[0][0], ah[0][1], ah[0][2], ah[0][3], ab);                     \
            LDX4(ah[1][0], ah[1][1], ah[1][2], ah[1][3], ab + 1024);              \
            LDX4(al[0][0], al[0][1], al[0][2], al[0][3], ab + OAL);               \
            LDX4(al[1][0], al[1][1], al[1][2], al[1][3], ab + OAL + 1024);        \
            _Pragma("unroll")                                                     \
            for (int m2 = 0; m2 < 2; m2++)                                        \
                _Pragma("unroll")                                                 \
                for (int nt = 0; nt < 4; nt++)                                    \
                    mma_bf16(acc[half * 2 + m2][nt], ah[m2], bh[nt]);             \
            _Pragma("unroll")                                                     \
            for (int m2 = 0; m2 < 2; m2++)                                        \
                _Pragma("unroll")                                                 \
                for (int nt = 0; nt < 4; nt++)                                    \
                    mma_bf16(acc[half * 2 + m2][nt], ah[m2], bl[nt]);             \
            _Pragma("unroll")                                                     \
            for (int m2 = 0; m2 < 2; m2++)                                        \
                _Pragma("unroll")                                                 \
                for (int nt = 0; nt < 4; nt++)                                    \
                    mma_bf16(acc[half * 2 + m2][nt], al[m2], bh[nt]);             \
        }                                                                         \
    }

    const int nchunks = Kpart >> 5;   // >= 16 always
    LOAD_CHUNK(0, 0); CP_COMMIT();
    LOAD_CHUNK(1, 1); CP_COMMIT();

    int buf = 0;                      // c % 3
    for (int c = 0; c < nchunks; c++) {
        CP_WAIT1();
        __syncthreads();
        const int cn = c + 2;
        int nbuf = buf + 2; if (nbuf >= 3) nbuf -= 3;
        if (cn < nchunks) LOAD_CHUNK(cn, nbuf);
        CP_COMMIT();
        const uint32_t bofs = (uint32_t)(buf * BUF_BYTES);
        COMPUTE_STEP(0, bofs);
        COMPUTE_STEP(1, bofs);
        if (++buf == 3) buf = 0;
    }

    // ---- epilogue
    const int frow = lane >> 2;
    const int fcol = (lane & 3) << 1;
#pragma unroll
    for (int mt = 0; mt < 4; mt++) {
        const int row = brow + wm * 64 + mt * 16 + frow;
#pragma unroll
        for (int nt = 0; nt < 4; nt++) {
            const int col = bcol + wn * 32 + nt * 8 + fcol;
            *(float2*)&C[(size_t)row * N + col] =
                make_float2(acc[mt][nt][0], acc[mt][nt][1]);
            *(float2*)&C[(size_t)(row + 8) * N + col] =
                make_float2(acc[mt][nt][2], acc[mt][nt][3]);
        }
    }
#undef LOAD_CHUNK
#undef COMPUTE_STEP
}

// ---------- split-K reduce: out = p0+p1+p2+p3 (float4) ----------------------
__global__ __launch_bounds__(256)
void reduce4_kernel(const float* __restrict__ p, float* __restrict__ out, int n4)
{
    int i = blockIdx.x * 256 + threadIdx.x;
    if (i >= n4) return;
    const float4* p0 = (const float4*)p;
    const float4* p1 = p0 + n4;
    const float4* p2 = p1 + n4;
    const float4* p3 = p2 + n4;
    float4 a = p0[i], b = p1[i], c = p2[i], d = p3[i];
    float4 r = make_float4(a.x + b.x + c.x + d.x, a.y + b.y + c.y + d.y,
                           a.z + b.z + c.z + d.z, a.w + b.w + c.w + d.w);
    ((float4*)out)[i] = r;
}

// ---------------- split helpers --------------------------------------------
__global__ __launch_bounds__(256)
void split_kernel(const float* __restrict__ src, __nv_bfloat16* __restrict__ hi,
                  __nv_bfloat16* __restrict__ lo, int n)
{
    int i = blockIdx.x * 256 + threadIdx.x;
    if (i >= n) return;
    float v = src[i];
    __nv_bfloat16 h = __float2bfloat16(v);
    hi[i] = h;
    lo[i] = __float2bfloat16(v - __bfloat162float(h));
}

// transpose + split: W[K,N] fp32 -> Th/Tl[N,K] bf16
__global__ __launch_bounds__(256)
void tsplit_kernel(const float* __restrict__ W, __nv_bfloat16* __restrict__ Th,
                   __nv_bfloat16* __restrict__ Tl, int K, int N)
{
    __shared__ float t[32][33];
    const int tx = threadIdx.x & 31;
    const int ty = threadIdx.x >> 5;
    const int n0 = blockIdx.x * 32;
    const int k0 = blockIdx.y * 32;
#pragma unroll
    for (int s2 = 0; s2 < 32; s2 += 8)
        t[ty + s2][tx] = W[(size_t)(k0 + ty + s2) * N + n0 + tx];
    __syncthreads();
#pragma unroll
    for (int s2 = 0; s2 < 32; s2 += 8) {
        float v = t[tx][ty + s2];
        __nv_bfloat16 h = __float2bfloat16(v);
        const size_t o = (size_t)(n0 + ty + s2) * K + k0 + tx;
        Th[o] = h;
        Tl[o] = __float2bfloat16(v - __bfloat162float(h));
    }
}

// ---------------- packed f32x2 helpers (FFMA2) ------------------------------
__device__ __forceinline__ unsigned long long pack_dup_f32(float x) {
    unsigned long long r;
    unsigned int u = __float_as_uint(x);
    asm("mov.b64 %0, {%1, %1};" : "=l"(r) : "r"(u));
    return r;
}
__device__ __forceinline__ unsigned long long fma_f32x2(
    unsigned long long a, unsigned long long b, unsigned long long c) {
    unsigned long long d;
    asm("fma.rn.f32x2 %0, %1, %2, %3;" : "=l"(d) : "l"(a), "l"(b), "l"(c));
    return d;
}
__device__ __forceinline__ float2 unpack_f32x2(unsigned long long v) {
    unsigned int lo, hi;
    asm("mov.b64 {%0, %1}, %2;" : "=r"(lo), "=r"(hi) : "l"(v));
    return make_float2(__uint_as_float(lo), __uint_as_float(hi));
}

// ---------------- FFMA2 GEMM (delta GEMM, K=64) -----------------------------
#define BK 16
template <int EPI>
__global__ __launch_bounds__(256, 2)
void sgemm128(const float* __restrict__ A, const float* __restrict__ B,
              const float* __restrict__ bias, float* __restrict__ C,
              int M, int N, int K, int lda, int ldb, int ldc)
{
    __shared__ __align__(16) float As[2][BK][128];
    __shared__ __align__(16) float Bs[2][BK][128];

    const int tid  = threadIdx.x;
    const int brow = blockIdx.y * 128;
    const int bcol = blockIdx.x * 128;

    const int arow = tid >> 1;
    const int acol = (tid & 1) << 3;
    const int bk = tid >> 4;
    const int bc = (tid & 15) << 3;
    const int tx = (tid & 15) << 3;
    const int ty = (tid >> 4) << 3;

    const float* Ap = A + (size_t)(brow + arow) * lda + acol;
    const float* Bp = B + (size_t)bk * ldb + bcol + bc;

    unsigned long long acc[8][4];
#pragma unroll
    for (int i = 0; i < 8; i++)
#pragma unroll
        for (int j = 0; j < 4; j++) acc[i][j] = 0ull;

    float4 a0 = *(const float4*)(Ap);
    float4 a1 = *(const float4*)(Ap + 4);
    float4 b0 = *(const float4*)(Bp);
    float4 b1 = *(const float4*)(Bp + 4);

#define STORE_TILE(bufi)                                            \
    {                                                               \
        As[bufi][acol + 0][arow] = a0.x;                            \
        As[bufi][acol + 1][arow] = a0.y;                            \
        As[bufi][acol + 2][arow] = a0.z;                            \
        As[bufi][acol + 3][arow] = a0.w;                            \
        As[bufi][acol + 4][arow] = a1.x;                            \
        As[bufi][acol + 5][arow] = a1.y;                            \
        As[bufi][acol + 6][arow] = a1.z;                            \
        As[bufi][acol + 7][arow] = a1.w;                            \
        *(float4*)&Bs[bufi][bk][bc]     = b0;                       \
        *(float4*)&Bs[bufi][bk][bc + 4] = b1;                       \
    }

#define COMPUTE_TILE(bufi)                                          \
    {                                                               \
        _Pragma("unroll")                                           \
        for (int kk = 0; kk < BK; kk++) {                           \
            float4 av0 = *(const float4*)&As[bufi][kk][ty];         \
            float4 av1 = *(const float4*)&As[bufi][kk][ty + 4];     \
            ulonglong2 bq01 = *(const ulonglong2*)&Bs[bufi][kk][tx];\
            ulonglong2 bq23 = *(const ulonglong2*)&Bs[bufi][kk][tx + 4];\
            unsigned long long bq[4] = {bq01.x, bq01.y, bq23.x, bq23.y};\
            float ar[8] = {av0.x, av0.y, av0.z, av0.w,              \
                           av1.x, av1.y, av1.z, av1.w};             \
            _Pragma("unroll")                                       \
            for (int i = 0; i < 8; i++) {                           \
                unsigned long long a2 = pack_dup_f32(ar[i]);        \
                _Pragma("unroll")                                   \
                for (int j = 0; j < 4; j++)                         \
                    acc[i][j] = fma_f32x2(a2, bq[j], acc[i][j]);    \
            }                                                       \
        }                                                           \
    }

    STORE_TILE(0);
    __syncthreads();

    int buf = 0;
    for (int k0 = BK; k0 < K; k0 += BK) {
        a0 = *(const float4*)(Ap + k0);
        a1 = *(const float4*)(Ap + k0 + 4);
        b0 = *(const float4*)(Bp + (size_t)k0 * ldb);
        b1 = *(const float4*)(Bp + (size_t)k0 * ldb + 4);
        COMPUTE_TILE(buf);
        STORE_TILE(buf ^ 1);
        __syncthreads();
        buf ^= 1;
    }
    COMPUTE_TILE(buf);

#pragma unroll
    for (int i = 0; i < 8; i++) {
        const int row = brow + ty + i;
#pragma unroll
        for (int j = 0; j < 4; j++) {
            float2 v = unpack_f32x2(acc[i][j]);
            const int col = bcol + tx + 2 * j;
            if (EPI == 1) {
                v.x += bias[col];
                v.y += bias[col + 1];
                v.x = (v.x > 20.f) ? v.x : log1pf(__expf(v.x));
                v.y = (v.y > 20.f) ? v.y : log1pf(__expf(v.y));
            }
            *(float2*)&C[(size_t)row * ldc + col] = v;
        }
    }
#undef STORE_TILE
#undef COMPUTE_TILE
}

// ---------- depthwise causal conv (k=4) + SiLU, plus silu(z) precompute ----
__global__ __launch_bounds__(256)
void conv_silu_kernel(const float* __restrict__ conv_w, const float* __restrict__ conv_b)
{
    int idx = blockIdx.x * blockDim.x + threadIdx.x;
    if (idx >= NROWS * D_INNER) return;
    const int d   = idx & (D_INNER - 1);
    const int row = idx >> 11;
    const int l   = row & (SEQ - 1);

    const float w0 = conv_w[d * 4 + 0];
    const float w1 = conv_w[d * 4 + 1];
    const float w2 = conv_w[d * 4 + 2];
    const float w3 = conv_w[d * 4 + 3];

    const float* xe = g_xz + (size_t)row * (2 * D_INNER) + d;
    float acc = conv_b[d];
    acc = fmaf(w3, xe[0], acc);
    if (l >= 1) acc = fmaf(w2, xe[-(2 * D_INNER)], acc);
    if (l >= 2) acc = fmaf(w1, xe[-2 * (2 * D_INNER)], acc);
    if (l >= 3) acc = fmaf(w0, xe[-3 * (2 * D_INNER)], acc);

    g_xc[idx] = acc / (1.f + __expf(-acc));

    const float zv = g_xz[(size_t)row * (2 * D_INNER) + D_INNER + d];
    g_zs[idx] = zv / (1.f + __expf(-zv));
}

// ---------- small-N GEMM: g_xdbl[2048,96] = g_xc @ W_x[2048,96] -------------
__global__ __launch_bounds__(256)
void gemm_n96(const float* __restrict__ Wx)
{
    __shared__ float Bs[64][32];
    const int tx  = threadIdx.x;
    const int ty  = threadIdx.y;
    const int tid = ty * 32 + tx;
    const int col = blockIdx.x * 32 + tx;
    const int row = blockIdx.y * 8 + ty;

    float acc = 0.f;
    const float* arow = g_xc + (size_t)row * D_INNER;

    for (int k0 = 0; k0 < D_INNER; k0 += 64) {
        for (int i = tid; i < 64 * 32; i += 256)
            Bs[i >> 5][i & 31] = Wx[(size_t)(k0 + (i >> 5)) * XDBL_N + blockIdx.x * 32 + (i & 31)];
        __syncthreads();
#pragma unroll
        for (int kk = 0; kk < 64; kk += 4) {
            float4 a4 = *(const float4*)(arow + k0 + kk);
            acc = fmaf(a4.x, Bs[kk + 0][tx], acc);
            acc = fmaf(a4.y, Bs[kk + 1][tx], acc);
            acc = fmaf(a4.z, Bs[kk + 2][tx], acc);
            acc = fmaf(a4.w, Bs[kk + 3][tx], acc);
        }
        __syncthreads();
    }
    if (col < XDBL_N) g_xdbl[(size_t)row * XDBL_N + col] = acc;
}

// ---------- selective scan: prefetched, writes y as bf16 hi/lo split --------
__global__ __launch_bounds__(256)
void scan_kernel(const float* __restrict__ A_log, const float* __restrict__ Dp)
{
    const int lane16 = threadIdx.x & 15;
    const int chan   = (blockIdx.x << 4) | (threadIdx.x >> 4);
    const int b      = blockIdx.y;

    const float Aval = -__expf(A_log[chan * D_STATE + lane16]);
    const float Dd   = Dp[chan];

    const float* dl = g_delta + (size_t)b * SEQ * D_INNER + chan;
    const float* xp = g_xc    + (size_t)b * SEQ * D_INNER + chan;
    const float* zp = g_zs    + (size_t)b * SEQ * D_INNER + chan;
    __nv_bfloat16* yh = g_yh  + (size_t)b * SEQ * D_INNER + chan;
    __nv_bfloat16* yl = g_yl  + (size_t)b * SEQ * D_INNER + chan;
    const float* bp = g_xdbl  + (size_t)b * SEQ * XDBL_N + DT_RANK + lane16;
    const float* cp = bp + D_STATE;

    // prefetch buffers (next 4 steps)
    float pdv[4], pxv[4], pzv[4], pBn[4], pCn[4];
#pragma unroll
    for (int u = 0; u < 4; u++) {
        pdv[u] = dl[u * D_INNER];
        pxv[u] = xp[u * D_INNER];
        pzv[u] = zp[u * D_INNER];
        pBn[u] = bp[u * XDBL_N];
        pCn[u] = cp[u * XDBL_N];
    }

    float h = 0.f;
    for (int l = 0; l < SEQ; l += 4) {
        float dv[4], xv[4], Bn[4], Cn[4], zv[4], dA[4];
#pragma unroll
        for (int u = 0; u < 4; u++) {
            dv[u] = pdv[u]; xv[u] = pxv[u]; zv[u] = pzv[u];
            Bn[u] = pBn[u]; Cn[u] = pCn[u];
        }
        // advance and prefetch next iteration (loads overlap compute below)
        dl += 4 * D_INNER; xp += 4 * D_INNER; zp += 4 * D_INNER;
        bp += 4 * XDBL_N;  cp += 4 * XDBL_N;
        if (l + 4 < SEQ) {
#pragma unroll
            for (int u = 0; u < 4; u++) {
                pdv[u] = dl[u * D_INNER];
                pxv[u] = xp[u * D_INNER];
                pzv[u] = zp[u * D_INNER];
                pBn[u] = bp[u * XDBL_N];
                pCn[u] = cp[u * XDBL_N];
            }
        }

#pragma unroll
        for (int u = 0; u < 4; u++)
            dA[u] = __expf(dv[u] * Aval);

        float contrib[4];
#pragma unroll
        for (int u = 0; u < 4; u++) {
            h = fmaf(dA[u], h, dv[u] * xv[u] * Bn[u]);
            contrib[u] = h * Cn[u];
        }
#pragma unroll
        for (int u = 0; u < 4; u++) {
            contrib[u] += __shfl_down_sync(0xffffffffu, contrib[u], 8, 16);
            contrib[u] += __shfl_down_sync(0xffffffffu, contrib[u], 4, 16);
            contrib[u] += __shfl_down_sync(0xffffffffu, contrib[u], 2, 16);
            contrib[u] += __shfl_down_sync(0xffffffffu, contrib[u], 1, 16);
        }
        if (lane16 == 0) {
#pragma unroll
            for (int u = 0; u < 4; u++) {
                float v = fmaf(xv[u], Dd, contrib[u]) * zv[u];
                __nv_bfloat16 hh = __float2bfloat16(v);
                yh[u * D_INNER] = hh;
                yl[u * D_INNER] = __float2bfloat16(v - __bfloat162float(hh));
            }
        }
        yh += 4 * D_INNER; yl += 4 * D_INNER;
    }
}

// ---------------- launch ----------------------------------------------------
extern "C" void kernel_launch(void* const* d_in, const int* in_sizes, int n_in,
                              void* d_out, int out_size)
{
    const float* x      = (const float*)d_in[0];
    const float* W_in   = (const float*)d_in[1];
    const float* conv_w = (const float*)d_in[2];
    const float* conv_b = (const float*)d_in[3];
    const float* W_x    = (const float*)d_in[4];
    const float* W_dt   = (const float*)d_in[5];
    const float* b_dt   = (const float*)d_in[6];
    const float* A_log  = (const float*)d_in[7];
    const float* Dp     = (const float*)d_in[8];
    const float* W_out  = (const float*)d_in[9];
    float* out = (float*)d_out;

    float *xz, *xdbl, *delta, *part;
    __nv_bfloat16 *xh, *xl, *winh, *winl, *yh, *yl, *woh, *wol;
    cudaGetSymbolAddress((void**)&xz,    g_xz);
    cudaGetSymbolAddress((void**)&xdbl,  g_xdbl);
    cudaGetSymbolAddress((void**)&delta, g_delta);
    cudaGetSymbolAddress((void**)&part,  g_part);
    cudaGetSymbolAddress((void**)&xh,   g_xh);
    cudaGetSymbolAddress((void**)&xl,   g_xl);
    cudaGetSymbolAddress((void**)&winh, g_winh);
    cudaGetSymbolAddress((void**)&winl, g_winl);
    cudaGetSymbolAddress((void**)&yh,   g_yh);
    cudaGetSymbolAddress((void**)&yl,   g_yl);
    cudaGetSymbolAddress((void**)&woh,  g_woh);
    cudaGetSymbolAddress((void**)&wol,  g_wol);

    const int HSMEM = 3 * BUF_BYTES;  // 98304 (3-stage)
    cudaFuncSetAttribute(hmma_gemm, cudaFuncAttributeMaxDynamicSharedMemorySize, HSMEM);

    // 0) bf16 splits of x and transposed weights
    split_kernel<<<(NROWS * D_MODEL + 255) / 256, 256>>>(x, xh, xl, NROWS * D_MODEL);
    tsplit_kernel<<<dim3(2 * D_INNER / 32, D_MODEL / 32), 256>>>(
        W_in, winh, winl, D_MODEL, 2 * D_INNER);
    tsplit_kernel<<<dim3(D_MODEL / 32, D_INNER / 32), 256>>>(
        W_out, woh, wol, D_INNER, D_MODEL);

    // 1) xz = x @ W_in   (HMMA split-bf16)   [2048,1024]@[1024,4096]
    hmma_gemm<<<dim3(2 * D_INNER / 128, NROWS / 128, 1), 256, HSMEM>>>(
        xh, xl, winh, winl, xz, D_MODEL, 2 * D_INNER, D_MODEL);

    // 2) xc = silu(conv(x_e)+b), zs = silu(z)
    conv_silu_kernel<<<(NROWS * D_INNER + 255) / 256, 256>>>(conv_w, conv_b);

    // 3) xdbl = xc @ W_x               [2048,2048]@[2048,96]
    gemm_n96<<<dim3(3, NROWS / 8), dim3(32, 8)>>>(W_x);

    // 4) delta = softplus(xdbl[:, :64] @ W_dt + b_dt)   K=64
    sgemm128<1><<<dim3(D_INNER / 128, NROWS / 128), 256>>>(
        xdbl, W_dt, b_dt, delta, NROWS, D_INNER, DT_RANK,
        XDBL_N, D_INNER, D_INNER);

    // 5) selective scan -> yh/yl bf16 split
    scan_kernel<<<dim3(D_INNER / 16, B_SZ), 256>>>(A_log, Dp);

    // 6) out = y @ W_out  (HMMA split-bf16, split-K=4)  [2048,2048]@[2048,1024]
    hmma_gemm<<<dim3(D_MODEL / 128, NROWS / 128, 4), 256, HSMEM>>>(
        yh, yl, woh, wol, part, D_INNER, D_MODEL, D_INNER / 4);
    reduce4_kernel<<<(NROWS * D_MODEL / 4 + 255) / 256, 256>>>(
        part, out, NROWS * D_MODEL / 4);
}